// round 12
// baseline (speedup 1.0000x reference)
#include <cuda_runtime.h>
#include <cuda_bf16.h>
#include <math.h>
#include <stdint.h>

#define HIDDEN 2048
#define NHEADS 16
#define HDIM   128
#define BATCH  2
#define SEQ    2048
#define BT     (BATCH*SEQ)   // 4096

// ---------------- scratch (static device arrays: no allocation) ----------------
__device__ float g_q[(size_t)BATCH*NHEADS*SEQ*HDIM];     // [B,H,T,D] fp32
__device__ float g_k[(size_t)BATCH*NHEADS*SEQ*HDIM];
__device__ float g_v[(size_t)BATCH*NHEADS*SEQ*HDIM];
__device__ float g_attn[(size_t)BT*HIDDEN];              // [B,T,C] fp32

__device__ __nv_bfloat16 g_xh[(size_t)BT*HIDDEN],  g_xl[(size_t)BT*HIDDEN];
__device__ __nv_bfloat16 g_ah[(size_t)BT*HIDDEN],  g_al[(size_t)BT*HIDDEN];
__device__ __nv_bfloat16 g_wqh[(size_t)HIDDEN*HIDDEN], g_wql[(size_t)HIDDEN*HIDDEN];
__device__ __nv_bfloat16 g_wkh[(size_t)HIDDEN*HIDDEN], g_wkl[(size_t)HIDDEN*HIDDEN];
__device__ __nv_bfloat16 g_wvh[(size_t)HIDDEN*HIDDEN], g_wvl[(size_t)HIDDEN*HIDDEN];
__device__ __nv_bfloat16 g_woh[(size_t)HIDDEN*HIDDEN], g_wol[(size_t)HIDDEN*HIDDEN];

// ======================= portable PTX helpers (sm_80+ ISA only) =======================
__device__ __forceinline__ uint32_t smem_u32(const void* p) {
    uint32_t a;
    asm("{ .reg .u64 t; cvta.to.shared.u64 t, %1; cvt.u32.u64 %0, t; }"
        : "=r"(a) : "l"(p));
    return a;
}

#define CP_ASYNC16(smaddr, gaddr) \
    asm volatile("cp.async.cg.shared.global [%0], [%1], 16;" \
        :: "r"(smaddr), "l"(gaddr))
#define CP_COMMIT() asm volatile("cp.async.commit_group;" ::: "memory")
#define CP_WAIT0()  asm volatile("cp.async.wait_group 0;"  ::: "memory")

#define LDMATRIX_X4(r0, r1, r2, r3, addr) \
    asm volatile("ldmatrix.sync.aligned.m8n8.x4.shared.b16 {%0,%1,%2,%3}, [%4];" \
        : "=r"(r0), "=r"(r1), "=r"(r2), "=r"(r3) : "r"(addr))

#define MMA_BF16(d, a, b) \
    asm volatile( \
        "mma.sync.aligned.m16n8k16.row.col.f32.bf16.bf16.f32 " \
        "{%0,%1,%2,%3}, {%4,%5,%6,%7}, {%8,%9}, {%0,%1,%2,%3};" \
        : "+f"((d)[0]), "+f"((d)[1]), "+f"((d)[2]), "+f"((d)[3]) \
        : "r"((a)[0]), "r"((a)[1]), "r"((a)[2]), "r"((a)[3]), \
          "r"((b)[0]), "r"((b)[1]))

// =================================================================================
// split fp32 -> bf16 hi + bf16 lo  (a = hi + lo + O(2^-18 a))
// =================================================================================
__global__ void split_bf16(const float* __restrict__ s, __nv_bfloat16* __restrict__ h,
                           __nv_bfloat16* __restrict__ l, int n4)
{
    int i = blockIdx.x * blockDim.x + threadIdx.x;
    if (i >= n4) return;
    float4 a = ((const float4*)s)[i];
    __nv_bfloat16 h0 = __float2bfloat16(a.x), h1 = __float2bfloat16(a.y);
    __nv_bfloat16 h2 = __float2bfloat16(a.z), h3 = __float2bfloat16(a.w);
    __nv_bfloat16 l0 = __float2bfloat16(a.x - __bfloat162float(h0));
    __nv_bfloat16 l1 = __float2bfloat16(a.y - __bfloat162float(h1));
    __nv_bfloat16 l2 = __float2bfloat16(a.z - __bfloat162float(h2));
    __nv_bfloat16 l3 = __float2bfloat16(a.w - __bfloat162float(h3));
    __nv_bfloat162 hv0, hv1, lv0, lv1;
    hv0.x = h0; hv0.y = h1; hv1.x = h2; hv1.y = h3;
    lv0.x = l0; lv0.y = l1; lv1.x = l2; lv1.y = l3;
    ((__nv_bfloat162*)h)[i * 2]     = hv0;
    ((__nv_bfloat162*)h)[i * 2 + 1] = hv1;
    ((__nv_bfloat162*)l)[i * 2]     = lv0;
    ((__nv_bfloat162*)l)[i * 2 + 1] = lv1;
}

// =================================================================================
// HMMA GEMM:  C[M,N] = A[M,K] * B[N,K]^T, bf16x3 emulated fp32 (3 mma per product).
// CTA tile 128x128, 8 warps (4 M x 2 N), warp tile 32x64, K-chunk 32 bf16,
// cp.async double-buffered smem, ldmatrix fragments.
// mode 0: C row-major [M,N]; mode 1: scatter to [B,H,T,D] (col tile 128 == head).
// =================================================================================
#define GPB    80                 // smem row pitch in bytes (32 bf16 data + 8 pad)
#define GTILE  (128 * GPB)        // 10240 B per tile
#define GSTAGE (4 * GTILE)        // Ah, Al, Bh, Bl  = 40960 B
#define GSMEM  (2 * GSTAGE)       // 81920 B

__device__ __forceinline__ void gemm_load_stage(
    uint32_t sbase, int buf,
    const __nv_bfloat16* __restrict__ Ah, const __nv_bfloat16* __restrict__ Al,
    const __nv_bfloat16* __restrict__ Bh, const __nv_bfloat16* __restrict__ Bl,
    int aRow0, int bRow0, int koff, int K, int tid)
{
    const uint32_t sb = sbase + buf * GSTAGE;
    #pragma unroll
    for (int it = 0; it < 2; it++) {
        const int q   = tid + it * 256;      // 0..511
        const int row = q >> 2;              // 0..127
        const int kc  = q & 3;               // 16B chunk in row
        const uint32_t so = row * GPB + kc * 16;
        const size_t ga = (size_t)(aRow0 + row) * K + koff + kc * 8;
        const size_t gb = (size_t)(bRow0 + row) * K + koff + kc * 8;
        CP_ASYNC16(sb + so,             (const void*)(Ah + ga));
        CP_ASYNC16(sb + GTILE + so,     (const void*)(Al + ga));
        CP_ASYNC16(sb + 2 * GTILE + so, (const void*)(Bh + gb));
        CP_ASYNC16(sb + 3 * GTILE + so, (const void*)(Bl + gb));
    }
}

__global__ void __launch_bounds__(256, 1)
gemm_mma(const __nv_bfloat16* __restrict__ Ah, const __nv_bfloat16* __restrict__ Al,
         const __nv_bfloat16* __restrict__ Bh, const __nv_bfloat16* __restrict__ Bl,
         float* __restrict__ C, int K, int N, int mode)
{
    extern __shared__ char sm[];
    const uint32_t sbase = smem_u32(sm);
    const int tid  = threadIdx.x;
    const int wid  = tid >> 5;
    const int lane = tid & 31;
    const int wm   = wid & 3;          // M block (32 rows)
    const int wn   = wid >> 2;         // N block (64 cols)
    const int bn   = blockIdx.x;
    const int bm   = blockIdx.y;
    const int aRow0 = bm * 128;
    const int bRow0 = bn * 128;
    const int NKC   = K >> 5;          // 64 chunks of 32

    float acc[2][8][4];
    #pragma unroll
    for (int mt = 0; mt < 2; mt++)
        #pragma unroll
        for (int nt = 0; nt < 8; nt++)
            #pragma unroll
            for (int e = 0; e < 4; e++) acc[mt][nt][e] = 0.0f;

    // per-lane ldmatrix addressing pieces
    const uint32_t lrow = lane & 15;
    const uint32_t lkh  = (lane >> 4) * 16;   // k-half byte offset within k16

    // preload chunk 0
    gemm_load_stage(sbase, 0, Ah, Al, Bh, Bl, aRow0, bRow0, 0, K, tid);
    CP_COMMIT();
    CP_WAIT0();
    __syncthreads();

    for (int c = 0; c < NKC; c++) {
        const int cur = c & 1;
        if (c + 1 < NKC) {
            gemm_load_stage(sbase, cur ^ 1, Ah, Al, Bh, Bl,
                            aRow0, bRow0, (c + 1) * 32, K, tid);
            CP_COMMIT();
        }

        const uint32_t abase = sbase + cur * GSTAGE;
        const uint32_t bbase = abase + 2 * GTILE;

        #pragma unroll
        for (int kk = 0; kk < 2; kk++) {
            const uint32_t ksel = kk * 32 + lkh;
            uint32_t ah_[2][4], al_[2][4];
            #pragma unroll
            for (int mt = 0; mt < 2; mt++) {
                const uint32_t ra = abase + (wm * 32 + mt * 16 + lrow) * GPB + ksel;
                LDMATRIX_X4(ah_[mt][0], ah_[mt][1], ah_[mt][2], ah_[mt][3], ra);
                LDMATRIX_X4(al_[mt][0], al_[mt][1], al_[mt][2], al_[mt][3], ra + GTILE);
            }
            uint32_t bh_[8][2], bl_[8][2];
            #pragma unroll
            for (int p = 0; p < 4; p++) {
                const uint32_t rb = bbase + (wn * 64 + p * 16 + lrow) * GPB + ksel;
                uint32_t r0, r1, r2, r3;
                LDMATRIX_X4(r0, r1, r2, r3, rb);
                bh_[2*p][0] = r0; bh_[2*p][1] = r2;
                bh_[2*p+1][0] = r1; bh_[2*p+1][1] = r3;
                LDMATRIX_X4(r0, r1, r2, r3, rb + GTILE);
                bl_[2*p][0] = r0; bl_[2*p][1] = r2;
                bl_[2*p+1][0] = r1; bl_[2*p+1][1] = r3;
            }
            #pragma unroll
            for (int mt = 0; mt < 2; mt++)
                #pragma unroll
                for (int nt = 0; nt < 8; nt++) {
                    MMA_BF16(acc[mt][nt], ah_[mt], bh_[nt]);
                    MMA_BF16(acc[mt][nt], ah_[mt], bl_[nt]);
                    MMA_BF16(acc[mt][nt], al_[mt], bh_[nt]);
                }
        }

        if (c + 1 < NKC) {
            CP_WAIT0();
            __syncthreads();
        }
    }

    // ---- epilogue ----
    const int tr = lane >> 2;          // 0..7
    const int tc = (lane & 3) * 2;     // 0,2,4,6
    #pragma unroll
    for (int mt = 0; mt < 2; mt++) {
        #pragma unroll
        for (int rr = 0; rr < 2; rr++) {
            const int m = aRow0 + wm * 32 + mt * 16 + rr * 8 + tr;
            float* dst;
            if (mode == 0) {
                dst = C + (size_t)m * N + bn * 128;
            } else {
                const int bb = m >> 11;
                const int t  = m & 2047;
                dst = C + ((((size_t)(bb * NHEADS + bn)) * SEQ + t) << 7);
            }
            #pragma unroll
            for (int nt = 0; nt < 8; nt++) {
                float2 v;
                v.x = acc[mt][nt][rr * 2 + 0];
                v.y = acc[mt][nt][rr * 2 + 1];
                *(float2*)(dst + wn * 64 + nt * 8 + tc) = v;
            }
        }
    }
}

// =================================================================================
// RoPE (in-place on q and k, layout [B,H,T,D], D=128, pairs (d, d+64))
// =================================================================================
__global__ void rope_kernel(float* __restrict__ q, float* __restrict__ k)
{
    const int idx = blockIdx.x * blockDim.x + threadIdx.x;
    const int i   = idx & 63;
    const int row = idx >> 6;
    const int t   = row & (SEQ - 1);

    const float inv = exp2f(-(float)i * 0.20762050593046014f);  // 10000^(-i/64)
    const float ang = (float)t * inv;
    float s, c;
    sincosf(ang, &s, &c);

    float* qp = q + (size_t)row * HDIM;
    float* kp = k + (size_t)row * HDIM;
    const float q1 = qp[i], q2 = qp[i + 64];
    qp[i]      = q1 * c - q2 * s;
    qp[i + 64] = q2 * c + q1 * s;
    const float k1 = kp[i], k2 = kp[i + 64];
    kp[i]      = k1 * c - k2 * s;
    kp[i + 64] = k2 * c + k1 * s;
}

// =================================================================================
// Flash attention, fp32, causal. BM=BN=64, D=128, 256 threads (2 warps/SMSP).
// =================================================================================
__global__ void __launch_bounds__(256, 1)
flash_attn(const float* __restrict__ q, const float* __restrict__ k,
           const float* __restrict__ v, float* __restrict__ outp)
{
    extern __shared__ float smf[];
    float* Qs = smf;                         // [64][129]
    float* Ks = smf + 64 * 129;              // [64][129]
    float* Vs = smf + 2 * 64 * 129;          // [64][132]
    float* Ps = Vs + 64 * 132;               // [64][65]
    float* row_m     = Ps + 64 * 65;         // [64]
    float* row_l     = row_m + 64;           // [64]
    float* row_alpha = row_l + 64;           // [64]

    const int tid = threadIdx.x;
    const int bh  = blockIdx.y;
    const int qi  = (gridDim.x - 1) - blockIdx.x;   // heavy q-tiles first
    const float scale = 0.08838834764831845f;       // 1/sqrt(128)

    const float* qbase = q + ((size_t)bh * SEQ + (size_t)qi * 64) * HDIM;
    for (int idx = tid; idx < 64 * HDIM / 4; idx += 256) {
        const int r = idx >> 5;
        const int c = (idx & 31) << 2;
        float4 t4 = *(const float4*)(qbase + r * HDIM + c);
        Qs[r * 129 + c + 0] = t4.x * scale;
        Qs[r * 129 + c + 1] = t4.y * scale;
        Qs[r * 129 + c + 2] = t4.z * scale;
        Qs[r * 129 + c + 3] = t4.w * scale;
    }
    if (tid < 64) { row_m[tid] = -1e30f; row_l[tid] = 0.0f; }

    float oacc[32];
    #pragma unroll
    for (int i = 0; i < 32; i++) oacc[i] = 0.0f;

    const int r_own = tid & 63;       // PV: owned row
    const int qtr   = tid >> 6;       // PV: 32-col quarter of D
    const int r0 = (tid >> 3) * 2;    // S micro-tile: 2 rows x 8 cols
    const int c0 = (tid & 7) * 8;

    __syncthreads();

    for (int j = 0; j <= qi; j++) {
        const float* kb = k + ((size_t)bh * SEQ + (size_t)j * 64) * HDIM;
        const float* vb = v + ((size_t)bh * SEQ + (size_t)j * 64) * HDIM;
        for (int idx = tid; idx < 64 * HDIM / 4; idx += 256) {
            const int r = idx >> 5;
            const int c = (idx & 31) << 2;
            float4 kt4 = *(const float4*)(kb + r * HDIM + c);
            Ks[r * 129 + c + 0] = kt4.x; Ks[r * 129 + c + 1] = kt4.y;
            Ks[r * 129 + c + 2] = kt4.z; Ks[r * 129 + c + 3] = kt4.w;
            float4 vt4 = *(const float4*)(vb + r * HDIM + c);
            *(float4*)&Vs[r * 132 + c] = vt4;
        }
        __syncthreads();

        // ---- S = Qs * Ks^T ----
        float sacc[2][8];
        #pragma unroll
        for (int i = 0; i < 2; i++)
            #pragma unroll
            for (int jj = 0; jj < 8; jj++) sacc[i][jj] = 0.0f;

        #pragma unroll 4
        for (int kk = 0; kk < HDIM; kk++) {
            float qf[2], kf[8];
            #pragma unroll
            for (int i = 0; i < 2; i++)  qf[i]  = Qs[(r0 + i) * 129 + kk];
            #pragma unroll
            for (int jj = 0; jj < 8; jj++) kf[jj] = Ks[(c0 + jj) * 129 + kk];
            #pragma unroll
            for (int i = 0; i < 2; i++)
                #pragma unroll
                for (int jj = 0; jj < 8; jj++)
                    sacc[i][jj] = fmaf(qf[i], kf[jj], sacc[i][jj]);
        }

        const bool diag = (j == qi);
        #pragma unroll
        for (int i = 0; i < 2; i++)
            #pragma unroll
            for (int jj = 0; jj < 8; jj++) {
                float sv = sacc[i][jj];
                if (diag && (c0 + jj) > (r0 + i)) sv = -1e30f;
                Ps[(r0 + i) * 65 + (c0 + jj)] = sv;
            }
        __syncthreads();

        // ---- online softmax (one thread per row) ----
        if (tid < 64) {
            const int r = tid;
            const float mold = row_m[r];
            float mx = mold;
            #pragma unroll 8
            for (int c = 0; c < 64; c++) mx = fmaxf(mx, Ps[r * 65 + c]);
            const float alpha = __expf(mold - mx);
            float sum = 0.0f;
            #pragma unroll 8
            for (int c = 0; c < 64; c++) {
                const float p = __expf(Ps[r * 65 + c] - mx);
                Ps[r * 65 + c] = p;
                sum += p;
            }
            row_l[r]     = row_l[r] * alpha + sum;
            row_m[r]     = mx;
            row_alpha[r] = alpha;
        }
        __syncthreads();

        // ---- O = O*alpha + P*V ----
        const float alpha = row_alpha[r_own];
        #pragma unroll
        for (int c = 0; c < 32; c++) oacc[c] *= alpha;

        #pragma unroll 2
        for (int kk = 0; kk < 64; kk++) {
            const float p = Ps[r_own * 65 + kk];
            const float4* vr = (const float4*)(Vs + kk * 132 + qtr * 32);
            #pragma unroll
            for (int c4 = 0; c4 < 8; c4++) {
                float4 vv = vr[c4];
                oacc[c4 * 4 + 0] = fmaf(p, vv.x, oacc[c4 * 4 + 0]);
                oacc[c4 * 4 + 1] = fmaf(p, vv.y, oacc[c4 * 4 + 1]);
                oacc[c4 * 4 + 2] = fmaf(p, vv.z, oacc[c4 * 4 + 2]);
                oacc[c4 * 4 + 3] = fmaf(p, vv.w, oacc[c4 * 4 + 3]);
            }
        }
        __syncthreads();
    }

    // ---- normalize + write to [B,T,C] ----
    const float invl = 1.0f / row_l[r_own];
    const int b = bh >> 4;
    const int h = bh & 15;
    const int t = qi * 64 + r_own;
    float* orow = outp + ((size_t)(b * SEQ + t)) * HIDDEN + h * HDIM + qtr * 32;
    #pragma unroll
    for (int c4 = 0; c4 < 8; c4++) {
        float4 o;
        o.x = oacc[c4 * 4 + 0] * invl;
        o.y = oacc[c4 * 4 + 1] * invl;
        o.z = oacc[c4 * 4 + 2] * invl;
        o.w = oacc[c4 * 4 + 3] * invl;
        *(float4*)(orow + c4 * 4) = o;
    }
}

// =================================================================================
// launch
// =================================================================================
extern "C" void kernel_launch(void* const* d_in, const int* in_sizes, int n_in,
                              void* d_out, int out_size)
{
    (void)in_sizes; (void)n_in; (void)out_size;
    const float* x  = (const float*)d_in[0];
    const float* Wq = (const float*)d_in[1];
    const float* Wk = (const float*)d_in[2];
    const float* Wv = (const float*)d_in[3];
    const float* Wo = (const float*)d_in[4];
    float* out = (float*)d_out;

    float *qp, *kp, *vp, *ap;
    __nv_bfloat16 *xh, *xl, *ah, *al;
    __nv_bfloat16 *wqh, *wql, *wkh, *wkl, *wvh, *wvl, *woh, *wol;
    cudaGetSymbolAddress((void**)&qp, g_q);
    cudaGetSymbolAddress((void**)&kp, g_k);
    cudaGetSymbolAddress((void**)&vp, g_v);
    cudaGetSymbolAddress((void**)&ap, g_attn);
    cudaGetSymbolAddress((void**)&xh, g_xh);  cudaGetSymbolAddress((void**)&xl, g_xl);
    cudaGetSymbolAddress((void**)&ah, g_ah);  cudaGetSymbolAddress((void**)&al, g_al);
    cudaGetSymbolAddress((void**)&wqh, g_wqh); cudaGetSymbolAddress((void**)&wql, g_wql);
    cudaGetSymbolAddress((void**)&wkh, g_wkh); cudaGetSymbolAddress((void**)&wkl, g_wkl);
    cudaGetSymbolAddress((void**)&wvh, g_wvh); cudaGetSymbolAddress((void**)&wvl, g_wvl);
    cudaGetSymbolAddress((void**)&woh, g_woh); cudaGetSymbolAddress((void**)&wol, g_wol);

    cudaFuncSetAttribute(gemm_mma, cudaFuncAttributeMaxDynamicSharedMemorySize, GSMEM);
    const int fa_smem = (2 * 64 * 129 + 64 * 132 + 64 * 65 + 3 * 64) * 4; // 117248
    cudaFuncSetAttribute(flash_attn, cudaFuncAttributeMaxDynamicSharedMemorySize, fa_smem);

    const int nx4 = BT * HIDDEN / 4;        // 2097152
    const int nw4 = HIDDEN * HIDDEN / 4;    // 1048576

    split_bf16<<<nx4 / 256, 256>>>(x,  xh,  xl,  nx4);
    split_bf16<<<nw4 / 256, 256>>>(Wq, wqh, wql, nw4);
    split_bf16<<<nw4 / 256, 256>>>(Wk, wkh, wkl, nw4);
    split_bf16<<<nw4 / 256, 256>>>(Wv, wvh, wvl, nw4);
    split_bf16<<<nw4 / 256, 256>>>(Wo, woh, wol, nw4);

    dim3 gg(HIDDEN / 128, BT / 128);   // (16, 32)
    gemm_mma<<<gg, 256, GSMEM>>>(xh, xl, wqh, wql, qp, HIDDEN, HIDDEN, 1);
    gemm_mma<<<gg, 256, GSMEM>>>(xh, xl, wkh, wkl, kp, HIDDEN, HIDDEN, 1);
    gemm_mma<<<gg, 256, GSMEM>>>(xh, xl, wvh, wvl, vp, HIDDEN, HIDDEN, 1);

    rope_kernel<<<(BATCH * NHEADS * SEQ * 64) / 256, 256>>>(qp, kp);

    flash_attn<<<dim3(SEQ / 64, BATCH * NHEADS), 256, fa_smem>>>(qp, kp, vp, ap);

    split_bf16<<<nx4 / 256, 256>>>(ap, ah, al, nx4);
    gemm_mma<<<gg, 256, GSMEM>>>(ah, al, woh, wol, out, HIDDEN, HIDDEN, 0);
}

// round 13
// speedup vs baseline: 1.9037x; 1.9037x over previous
#include <cuda_runtime.h>
#include <cuda_bf16.h>
#include <math.h>
#include <stdint.h>

#define HIDDEN 2048
#define NHEADS 16
#define HDIM   128
#define BATCH  2
#define SEQ    2048
#define BT     (BATCH*SEQ)   // 4096

// ---------------- scratch (static device arrays: no allocation) ----------------
__device__ float g_q[(size_t)BATCH*NHEADS*SEQ*HDIM];     // [B,H,T,D] fp32
__device__ float g_k[(size_t)BATCH*NHEADS*SEQ*HDIM];
__device__ float g_v[(size_t)BATCH*NHEADS*SEQ*HDIM];
__device__ float g_attn[(size_t)BT*HIDDEN];              // [B,T,C] fp32

__device__ __nv_bfloat16 g_xh[(size_t)BT*HIDDEN],  g_xl[(size_t)BT*HIDDEN];
__device__ __nv_bfloat16 g_ah[(size_t)BT*HIDDEN],  g_al[(size_t)BT*HIDDEN];
__device__ __nv_bfloat16 g_wqh[(size_t)HIDDEN*HIDDEN], g_wql[(size_t)HIDDEN*HIDDEN];
__device__ __nv_bfloat16 g_wkh[(size_t)HIDDEN*HIDDEN], g_wkl[(size_t)HIDDEN*HIDDEN];
__device__ __nv_bfloat16 g_wvh[(size_t)HIDDEN*HIDDEN], g_wvl[(size_t)HIDDEN*HIDDEN];
__device__ __nv_bfloat16 g_woh[(size_t)HIDDEN*HIDDEN], g_wol[(size_t)HIDDEN*HIDDEN];

// bf16 hi/lo splits of roped Q/K and V, layout [B,H,T,D]
__device__ __nv_bfloat16 g_qbh[(size_t)BT*HIDDEN], g_qbl[(size_t)BT*HIDDEN];
__device__ __nv_bfloat16 g_kbh[(size_t)BT*HIDDEN], g_kbl[(size_t)BT*HIDDEN];
__device__ __nv_bfloat16 g_vbh[(size_t)BT*HIDDEN], g_vbl[(size_t)BT*HIDDEN];

// ======================= portable PTX helpers (sm_80+ ISA only) =======================
__device__ __forceinline__ uint32_t smem_u32(const void* p) {
    uint32_t a;
    asm("{ .reg .u64 t; cvta.to.shared.u64 t, %1; cvt.u32.u64 %0, t; }"
        : "=r"(a) : "l"(p));
    return a;
}

#define CP_ASYNC16(smaddr, gaddr) \
    asm volatile("cp.async.cg.shared.global [%0], [%1], 16;" \
        :: "r"(smaddr), "l"(gaddr))
#define CP_COMMIT() asm volatile("cp.async.commit_group;" ::: "memory")
#define CP_WAIT0()  asm volatile("cp.async.wait_group 0;"  ::: "memory")
#define CP_WAIT1()  asm volatile("cp.async.wait_group 1;"  ::: "memory")

#define LDMATRIX_X4(r0, r1, r2, r3, addr) \
    asm volatile("ldmatrix.sync.aligned.m8n8.x4.shared.b16 {%0,%1,%2,%3}, [%4];" \
        : "=r"(r0), "=r"(r1), "=r"(r2), "=r"(r3) : "r"(addr))

#define LDMATRIX_X4_T(r0, r1, r2, r3, addr) \
    asm volatile("ldmatrix.sync.aligned.m8n8.x4.trans.shared.b16 {%0,%1,%2,%3}, [%4];" \
        : "=r"(r0), "=r"(r1), "=r"(r2), "=r"(r3) : "r"(addr))

#define MMA_BF16(d, a, b) \
    asm volatile( \
        "mma.sync.aligned.m16n8k16.row.col.f32.bf16.bf16.f32 " \
        "{%0,%1,%2,%3}, {%4,%5,%6,%7}, {%8,%9}, {%0,%1,%2,%3};" \
        : "+f"((d)[0]), "+f"((d)[1]), "+f"((d)[2]), "+f"((d)[3]) \
        : "r"((a)[0]), "r"((a)[1]), "r"((a)[2]), "r"((a)[3]), \
          "r"((b)[0]), "r"((b)[1]))

__device__ __forceinline__ void split2_bf16(float a, float b, uint32_t& hi, uint32_t& lo) {
    __nv_bfloat16 ha = __float2bfloat16(a), hb = __float2bfloat16(b);
    __nv_bfloat162 hv, lv;
    hv.x = ha; hv.y = hb;
    lv.x = __float2bfloat16(a - __bfloat162float(ha));
    lv.y = __float2bfloat16(b - __bfloat162float(hb));
    hi = *reinterpret_cast<uint32_t*>(&hv);
    lo = *reinterpret_cast<uint32_t*>(&lv);
}

// =================================================================================
// split fp32 -> bf16 hi + bf16 lo  (a = hi + lo + O(2^-18 a))
// =================================================================================
__global__ void split_bf16(const float* __restrict__ s, __nv_bfloat16* __restrict__ h,
                           __nv_bfloat16* __restrict__ l, int n4)
{
    int i = blockIdx.x * blockDim.x + threadIdx.x;
    if (i >= n4) return;
    float4 a = ((const float4*)s)[i];
    __nv_bfloat16 h0 = __float2bfloat16(a.x), h1 = __float2bfloat16(a.y);
    __nv_bfloat16 h2 = __float2bfloat16(a.z), h3 = __float2bfloat16(a.w);
    __nv_bfloat16 l0 = __float2bfloat16(a.x - __bfloat162float(h0));
    __nv_bfloat16 l1 = __float2bfloat16(a.y - __bfloat162float(h1));
    __nv_bfloat16 l2 = __float2bfloat16(a.z - __bfloat162float(h2));
    __nv_bfloat16 l3 = __float2bfloat16(a.w - __bfloat162float(h3));
    __nv_bfloat162 hv0, hv1, lv0, lv1;
    hv0.x = h0; hv0.y = h1; hv1.x = h2; hv1.y = h3;
    lv0.x = l0; lv0.y = l1; lv1.x = l2; lv1.y = l3;
    ((__nv_bfloat162*)h)[i * 2]     = hv0;
    ((__nv_bfloat162*)h)[i * 2 + 1] = hv1;
    ((__nv_bfloat162*)l)[i * 2]     = lv0;
    ((__nv_bfloat162*)l)[i * 2 + 1] = lv1;
}

// =================================================================================
// HMMA GEMM:  C[M,N] = A[M,K] * B[N,K]^T, bf16x3 emulated fp32.
// CTA tile 128x128, 8 warps (4 M x 2 N), warp tile 32x64, K-chunk 32 bf16,
// 3-stage cp.async pipeline (wait_group 1), ldmatrix fragments.
// =================================================================================
#define GPB    80                 // smem row pitch bytes
#define GTILE  (128 * GPB)        // 10240 B per tile
#define GSTAGE (4 * GTILE)        // Ah, Al, Bh, Bl  = 40960 B
#define GSMEM  (3 * GSTAGE)       // 122880 B

__device__ __forceinline__ void gemm_load_stage(
    uint32_t sbase, int buf,
    const __nv_bfloat16* __restrict__ Ah, const __nv_bfloat16* __restrict__ Al,
    const __nv_bfloat16* __restrict__ Bh, const __nv_bfloat16* __restrict__ Bl,
    int aRow0, int bRow0, int koff, int K, int tid)
{
    const uint32_t sb = sbase + buf * GSTAGE;
    #pragma unroll
    for (int it = 0; it < 2; it++) {
        const int q   = tid + it * 256;      // 0..511
        const int row = q >> 2;              // 0..127
        const int kc  = q & 3;               // 16B chunk in row
        const uint32_t so = row * GPB + kc * 16;
        const size_t ga = (size_t)(aRow0 + row) * K + koff + kc * 8;
        const size_t gb = (size_t)(bRow0 + row) * K + koff + kc * 8;
        CP_ASYNC16(sb + so,             (const void*)(Ah + ga));
        CP_ASYNC16(sb + GTILE + so,     (const void*)(Al + ga));
        CP_ASYNC16(sb + 2 * GTILE + so, (const void*)(Bh + gb));
        CP_ASYNC16(sb + 3 * GTILE + so, (const void*)(Bl + gb));
    }
}

__global__ void __launch_bounds__(256, 1)
gemm_mma(const __nv_bfloat16* __restrict__ Ah, const __nv_bfloat16* __restrict__ Al,
         const __nv_bfloat16* __restrict__ Bh, const __nv_bfloat16* __restrict__ Bl,
         float* __restrict__ C, int K, int N, int mode)
{
    extern __shared__ char sm[];
    const uint32_t sbase = smem_u32(sm);
    const int tid  = threadIdx.x;
    const int wid  = tid >> 5;
    const int lane = tid & 31;
    const int wm   = wid & 3;
    const int wn   = wid >> 2;
    const int bn   = blockIdx.x;
    const int bm   = blockIdx.y;
    const int aRow0 = bm * 128;
    const int bRow0 = bn * 128;
    const int NKC   = K >> 5;

    float acc[2][8][4];
    #pragma unroll
    for (int mt = 0; mt < 2; mt++)
        #pragma unroll
        for (int nt = 0; nt < 8; nt++)
            #pragma unroll
            for (int e = 0; e < 4; e++) acc[mt][nt][e] = 0.0f;

    const uint32_t lrow = lane & 15;
    const uint32_t lkh  = (lane >> 4) * 16;

    // preload stages 0, 1
    gemm_load_stage(sbase, 0, Ah, Al, Bh, Bl, aRow0, bRow0, 0,  K, tid); CP_COMMIT();
    gemm_load_stage(sbase, 1, Ah, Al, Bh, Bl, aRow0, bRow0, 32, K, tid); CP_COMMIT();

    for (int c = 0; c < NKC; c++) {
        if (c + 1 < NKC) { CP_WAIT1(); } else { CP_WAIT0(); }
        __syncthreads();

        if (c + 2 < NKC) {
            gemm_load_stage(sbase, (c + 2) % 3, Ah, Al, Bh, Bl,
                            aRow0, bRow0, (c + 2) * 32, K, tid);
            CP_COMMIT();
        }

        const uint32_t abase = sbase + (c % 3) * GSTAGE;
        const uint32_t bbase = abase + 2 * GTILE;

        #pragma unroll
        for (int kk = 0; kk < 2; kk++) {
            const uint32_t ksel = kk * 32 + lkh;
            uint32_t ah_[2][4], al_[2][4];
            #pragma unroll
            for (int mt = 0; mt < 2; mt++) {
                const uint32_t ra = abase + (wm * 32 + mt * 16 + lrow) * GPB + ksel;
                LDMATRIX_X4(ah_[mt][0], ah_[mt][1], ah_[mt][2], ah_[mt][3], ra);
                LDMATRIX_X4(al_[mt][0], al_[mt][1], al_[mt][2], al_[mt][3], ra + GTILE);
            }
            uint32_t bh_[8][2], bl_[8][2];
            #pragma unroll
            for (int p = 0; p < 4; p++) {
                const uint32_t rb = bbase + (wn * 64 + p * 16 + lrow) * GPB + ksel;
                uint32_t r0, r1, r2, r3;
                LDMATRIX_X4(r0, r1, r2, r3, rb);
                bh_[2*p][0] = r0; bh_[2*p][1] = r2;
                bh_[2*p+1][0] = r1; bh_[2*p+1][1] = r3;
                LDMATRIX_X4(r0, r1, r2, r3, rb + GTILE);
                bl_[2*p][0] = r0; bl_[2*p][1] = r2;
                bl_[2*p+1][0] = r1; bl_[2*p+1][1] = r3;
            }
            #pragma unroll
            for (int mt = 0; mt < 2; mt++)
                #pragma unroll
                for (int nt = 0; nt < 8; nt++) {
                    MMA_BF16(acc[mt][nt], ah_[mt], bh_[nt]);
                    MMA_BF16(acc[mt][nt], ah_[mt], bl_[nt]);
                    MMA_BF16(acc[mt][nt], al_[mt], bh_[nt]);
                }
        }
    }

    // ---- epilogue ----
    const int tr = lane >> 2;
    const int tc = (lane & 3) * 2;
    #pragma unroll
    for (int mt = 0; mt < 2; mt++) {
        #pragma unroll
        for (int rr = 0; rr < 2; rr++) {
            const int m = aRow0 + wm * 32 + mt * 16 + rr * 8 + tr;
            float* dst;
            if (mode == 0) {
                dst = C + (size_t)m * N + bn * 128;
            } else {
                const int bb = m >> 11;
                const int t  = m & 2047;
                dst = C + ((((size_t)(bb * NHEADS + bn)) * SEQ + t) << 7);
            }
            #pragma unroll
            for (int nt = 0; nt < 8; nt++) {
                float2 v;
                v.x = acc[mt][nt][rr * 2 + 0];
                v.y = acc[mt][nt][rr * 2 + 1];
                *(float2*)(dst + wn * 64 + nt * 8 + tc) = v;
            }
        }
    }
}

// =================================================================================
// RoPE + split: reads fp32 q,k [B,H,T,D], writes bf16 hi/lo splits (unscaled).
// =================================================================================
__global__ void rope_split(const float* __restrict__ q, const float* __restrict__ k,
                           __nv_bfloat16* __restrict__ qbh, __nv_bfloat16* __restrict__ qbl,
                           __nv_bfloat16* __restrict__ kbh, __nv_bfloat16* __restrict__ kbl)
{
    const int idx = blockIdx.x * blockDim.x + threadIdx.x;
    const int i   = idx & 63;
    const int row = idx >> 6;
    const int t   = row & (SEQ - 1);

    const float inv = exp2f(-(float)i * 0.20762050593046014f);  // 10000^(-i/64)
    const float ang = (float)t * inv;
    float s, c;
    sincosf(ang, &s, &c);

    const size_t base = (size_t)row * HDIM;
    const float q1 = q[base + i], q2 = q[base + i + 64];
    const float k1 = k[base + i], k2 = k[base + i + 64];
    const float qa = q1 * c - q2 * s, qb = q2 * c + q1 * s;
    const float ka = k1 * c - k2 * s, kb = k2 * c + k1 * s;

    __nv_bfloat16 h;
    h = __float2bfloat16(qa); qbh[base + i]      = h; qbl[base + i]      = __float2bfloat16(qa - __bfloat162float(h));
    h = __float2bfloat16(qb); qbh[base + i + 64] = h; qbl[base + i + 64] = __float2bfloat16(qb - __bfloat162float(h));
    h = __float2bfloat16(ka); kbh[base + i]      = h; kbl[base + i]      = __float2bfloat16(ka - __bfloat162float(h));
    h = __float2bfloat16(kb); kbh[base + i + 64] = h; kbl[base + i + 64] = __float2bfloat16(kb - __bfloat162float(h));
}

// =================================================================================
// HMMA flash attention, causal, bf16x3. BM=128 (8 warps x 16 rows), BN=64, D=128.
// Double-buffered K/V stages (cp.async). Output fp32 [B,T,C].
// =================================================================================
#define FPB      272                  // smem row pitch bytes (136 bf16)
#define FQ_TILE  (128 * FPB)          // 34816
#define FKV_TILE (64 * FPB)           // 17408
#define FSM_KV(s) (2 * FQ_TILE + (s) * (4 * FKV_TILE))
#define FSMEM    (2 * FQ_TILE + 2 * 4 * FKV_TILE)   // 208896

__device__ __forceinline__ void fa_load_kv(
    uint32_t sbase, int s,
    const __nv_bfloat16* __restrict__ kh, const __nv_bfloat16* __restrict__ kl,
    const __nv_bfloat16* __restrict__ vh, const __nv_bfloat16* __restrict__ vl,
    size_t off, int tid)
{
    const uint32_t sb = sbase + FSM_KV(s);
    #pragma unroll
    for (int it = 0; it < 4; it++) {
        const int q   = tid + it * 256;   // 0..1023
        const int row = q >> 4;           // 0..63
        const int ck  = q & 15;
        const uint32_t so = row * FPB + ck * 16;
        const size_t go = off + (size_t)row * HDIM + ck * 8;
        CP_ASYNC16(sb + so,                (const void*)(kh + go));
        CP_ASYNC16(sb + FKV_TILE + so,     (const void*)(kl + go));
        CP_ASYNC16(sb + 2 * FKV_TILE + so, (const void*)(vh + go));
        CP_ASYNC16(sb + 3 * FKV_TILE + so, (const void*)(vl + go));
    }
}

__global__ void __launch_bounds__(256, 1)
flash_mma(const __nv_bfloat16* __restrict__ qh, const __nv_bfloat16* __restrict__ ql,
          const __nv_bfloat16* __restrict__ kh, const __nv_bfloat16* __restrict__ kl,
          const __nv_bfloat16* __restrict__ vh, const __nv_bfloat16* __restrict__ vl,
          float* __restrict__ outp)
{
    extern __shared__ char sm[];
    const uint32_t sbase = smem_u32(sm);
    const int tid  = threadIdx.x;
    const int wid  = tid >> 5;
    const int lane = tid & 31;
    const int bh   = blockIdx.y;
    const int qi   = (gridDim.x - 1) - blockIdx.x;   // heavy q-tiles first
    const float scale = 0.08838834764831845f;        // 1/sqrt(128)

    // ---- load Q hi/lo into smem ----
    const size_t qoff = ((size_t)bh * SEQ + (size_t)qi * 128) * HDIM;
    for (int idx = tid; idx < 128 * 16; idx += 256) {
        const int row = idx >> 4, ck = idx & 15;
        const uint32_t so = row * FPB + ck * 16;
        *(uint4*)(sm + so)           = *(const uint4*)(qh + qoff + (size_t)row * HDIM + ck * 8);
        *(uint4*)(sm + FQ_TILE + so) = *(const uint4*)(ql + qoff + (size_t)row * HDIM + ck * 8);
    }

    const int nkv = 2 * qi + 2;
    const size_t bhoff = (size_t)bh * SEQ * HDIM;
    fa_load_kv(sbase, 0, kh, kl, vh, vl, bhoff, tid);               CP_COMMIT();
    fa_load_kv(sbase, 1, kh, kl, vh, vl, bhoff + 64 * HDIM, tid);   CP_COMMIT();

    float oacc[16][4];
    #pragma unroll
    for (int nt = 0; nt < 16; nt++)
        #pragma unroll
        for (int e = 0; e < 4; e++) oacc[nt][e] = 0.0f;
    float m1 = -1e30f, m2 = -1e30f, l1 = 0.0f, l2 = 0.0f;

    const int r1 = lane >> 2;            // 0..7
    const int c2 = (lane & 3) * 2;
    const uint32_t qrow = sbase + (wid * 16 + (lane & 15)) * FPB + (lane >> 4) * 16;
    const uint32_t lrow_off = (lane & 15) * FPB + (lane >> 4) * 16;

    for (int j = 0; j < nkv; j++) {
        if (j + 1 < nkv) { CP_WAIT1(); } else { CP_WAIT0(); }
        __syncthreads();

        const uint32_t kvb = sbase + FSM_KV(j & 1);
        const bool active = (j * 64 <= qi * 128 + wid * 16 + 15);
        if (active) {
            // ---- S = Q K^T (3-term bf16) ----
            float sacc[8][4];
            #pragma unroll
            for (int nt = 0; nt < 8; nt++)
                #pragma unroll
                for (int e = 0; e < 4; e++) sacc[nt][e] = 0.0f;

            const uint32_t krow = kvb + lrow_off;
            #pragma unroll
            for (int kd = 0; kd < 8; kd++) {
                uint32_t ah4[4], al4[4];
                LDMATRIX_X4(ah4[0], ah4[1], ah4[2], ah4[3], qrow + kd * 32);
                LDMATRIX_X4(al4[0], al4[1], al4[2], al4[3], qrow + FQ_TILE + kd * 32);
                #pragma unroll
                for (int p = 0; p < 4; p++) {
                    uint32_t t0, t1, t2, t3;
                    uint32_t bhf[2][2], blf[2][2];
                    LDMATRIX_X4(t0, t1, t2, t3, krow + p * (16 * FPB) + kd * 32);
                    bhf[0][0] = t0; bhf[0][1] = t2; bhf[1][0] = t1; bhf[1][1] = t3;
                    LDMATRIX_X4(t0, t1, t2, t3, krow + FKV_TILE + p * (16 * FPB) + kd * 32);
                    blf[0][0] = t0; blf[0][1] = t2; blf[1][0] = t1; blf[1][1] = t3;
                    MMA_BF16(sacc[2*p],   ah4, bhf[0]);
                    MMA_BF16(sacc[2*p],   ah4, blf[0]);
                    MMA_BF16(sacc[2*p],   al4, bhf[0]);
                    MMA_BF16(sacc[2*p+1], ah4, bhf[1]);
                    MMA_BF16(sacc[2*p+1], ah4, blf[1]);
                    MMA_BF16(sacc[2*p+1], al4, bhf[1]);
                }
            }

            // ---- scale + causal mask + online softmax ----
            const bool need_mask = (j * 64 + 63 > qi * 128 + wid * 16);
            const int grow1 = qi * 128 + wid * 16 + r1;
            float mx1 = m1, mx2 = m2;
            #pragma unroll
            for (int nt = 0; nt < 8; nt++) {
                #pragma unroll
                for (int e = 0; e < 4; e++) sacc[nt][e] *= scale;
                if (need_mask) {
                    const int col = j * 64 + nt * 8 + c2;
                    if (col     > grow1)     sacc[nt][0] = -1e30f;
                    if (col + 1 > grow1)     sacc[nt][1] = -1e30f;
                    if (col     > grow1 + 8) sacc[nt][2] = -1e30f;
                    if (col + 1 > grow1 + 8) sacc[nt][3] = -1e30f;
                }
                mx1 = fmaxf(mx1, fmaxf(sacc[nt][0], sacc[nt][1]));
                mx2 = fmaxf(mx2, fmaxf(sacc[nt][2], sacc[nt][3]));
            }
            mx1 = fmaxf(mx1, __shfl_xor_sync(0xffffffffu, mx1, 1));
            mx1 = fmaxf(mx1, __shfl_xor_sync(0xffffffffu, mx1, 2));
            mx2 = fmaxf(mx2, __shfl_xor_sync(0xffffffffu, mx2, 1));
            mx2 = fmaxf(mx2, __shfl_xor_sync(0xffffffffu, mx2, 2));

            const float alpha1 = __expf(m1 - mx1);
            const float alpha2 = __expf(m2 - mx2);
            m1 = mx1; m2 = mx2;

            float sum1 = 0.0f, sum2 = 0.0f;
            #pragma unroll
            for (int nt = 0; nt < 8; nt++) {
                sacc[nt][0] = __expf(sacc[nt][0] - mx1);
                sacc[nt][1] = __expf(sacc[nt][1] - mx1);
                sacc[nt][2] = __expf(sacc[nt][2] - mx2);
                sacc[nt][3] = __expf(sacc[nt][3] - mx2);
                sum1 += sacc[nt][0] + sacc[nt][1];
                sum2 += sacc[nt][2] + sacc[nt][3];
            }
            l1 = l1 * alpha1 + sum1;    // per-lane partial; quad-reduced at end
            l2 = l2 * alpha2 + sum2;

            #pragma unroll
            for (int nt = 0; nt < 16; nt++) {
                oacc[nt][0] *= alpha1; oacc[nt][1] *= alpha1;
                oacc[nt][2] *= alpha2; oacc[nt][3] *= alpha2;
            }

            // ---- O += P V (3-term bf16) ----
            const uint32_t vbase = kvb + 2 * FKV_TILE;
            #pragma unroll
            for (int g = 0; g < 4; g++) {
                uint32_t pha[4], pla[4];
                split2_bf16(sacc[2*g][0],   sacc[2*g][1],   pha[0], pla[0]);
                split2_bf16(sacc[2*g][2],   sacc[2*g][3],   pha[1], pla[1]);
                split2_bf16(sacc[2*g+1][0], sacc[2*g+1][1], pha[2], pla[2]);
                split2_bf16(sacc[2*g+1][2], sacc[2*g+1][3], pha[3], pla[3]);

                const uint32_t va = vbase + g * (16 * FPB) + lrow_off;
                #pragma unroll
                for (int pp = 0; pp < 8; pp++) {
                    uint32_t t0, t1, t2, t3;
                    LDMATRIX_X4_T(t0, t1, t2, t3, va + pp * 32);
                    uint32_t vh0[2] = { t0, t1 }, vh1[2] = { t2, t3 };
                    LDMATRIX_X4_T(t0, t1, t2, t3, va + FKV_TILE + pp * 32);
                    uint32_t vl0[2] = { t0, t1 }, vl1[2] = { t2, t3 };
                    MMA_BF16(oacc[2*pp],   pha, vh0);
                    MMA_BF16(oacc[2*pp],   pla, vh0);
                    MMA_BF16(oacc[2*pp],   pha, vl0);
                    MMA_BF16(oacc[2*pp+1], pha, vh1);
                    MMA_BF16(oacc[2*pp+1], pla, vh1);
                    MMA_BF16(oacc[2*pp+1], pha, vl1);
                }
            }
        }
        __syncthreads();    // all reads of stage (j&1) done before overwrite
        if (j + 2 < nkv) {
            fa_load_kv(sbase, j & 1, kh, kl, vh, vl,
                       bhoff + (size_t)(j + 2) * 64 * HDIM, tid);
            CP_COMMIT();
        }
    }

    // ---- finalize: quad-reduce l, normalize, write [B,T,C] ----
    l1 += __shfl_xor_sync(0xffffffffu, l1, 1);
    l1 += __shfl_xor_sync(0xffffffffu, l1, 2);
    l2 += __shfl_xor_sync(0xffffffffu, l2, 1);
    l2 += __shfl_xor_sync(0xffffffffu, l2, 2);
    const float inv1 = 1.0f / l1;
    const float inv2 = 1.0f / l2;

    const int b = bh >> 4;
    const int h = bh & 15;
    const int row1 = qi * 128 + wid * 16 + r1;
    float* o1 = outp + ((size_t)(b * SEQ + row1)) * HIDDEN + h * HDIM;
    float* o2 = o1 + 8 * HIDDEN;
    #pragma unroll
    for (int nt = 0; nt < 16; nt++) {
        float2 v1, v2;
        v1.x = oacc[nt][0] * inv1; v1.y = oacc[nt][1] * inv1;
        v2.x = oacc[nt][2] * inv2; v2.y = oacc[nt][3] * inv2;
        *(float2*)(o1 + nt * 8 + c2) = v1;
        *(float2*)(o2 + nt * 8 + c2) = v2;
    }
}

// =================================================================================
// launch
// =================================================================================
extern "C" void kernel_launch(void* const* d_in, const int* in_sizes, int n_in,
                              void* d_out, int out_size)
{
    (void)in_sizes; (void)n_in; (void)out_size;
    const float* x  = (const float*)d_in[0];
    const float* Wq = (const float*)d_in[1];
    const float* Wk = (const float*)d_in[2];
    const float* Wv = (const float*)d_in[3];
    const float* Wo = (const float*)d_in[4];
    float* out = (float*)d_out;

    float *qp, *kp, *vp, *ap;
    __nv_bfloat16 *xh, *xl, *ah, *al;
    __nv_bfloat16 *wqh, *wql, *wkh, *wkl, *wvh, *wvl, *woh, *wol;
    __nv_bfloat16 *qbh, *qbl, *kbh, *kbl, *vbh, *vbl;
    cudaGetSymbolAddress((void**)&qp, g_q);
    cudaGetSymbolAddress((void**)&kp, g_k);
    cudaGetSymbolAddress((void**)&vp, g_v);
    cudaGetSymbolAddress((void**)&ap, g_attn);
    cudaGetSymbolAddress((void**)&xh, g_xh);  cudaGetSymbolAddress((void**)&xl, g_xl);
    cudaGetSymbolAddress((void**)&ah, g_ah);  cudaGetSymbolAddress((void**)&al, g_al);
    cudaGetSymbolAddress((void**)&wqh, g_wqh); cudaGetSymbolAddress((void**)&wql, g_wql);
    cudaGetSymbolAddress((void**)&wkh, g_wkh); cudaGetSymbolAddress((void**)&wkl, g_wkl);
    cudaGetSymbolAddress((void**)&wvh, g_wvh); cudaGetSymbolAddress((void**)&wvl, g_wvl);
    cudaGetSymbolAddress((void**)&woh, g_woh); cudaGetSymbolAddress((void**)&wol, g_wol);
    cudaGetSymbolAddress((void**)&qbh, g_qbh); cudaGetSymbolAddress((void**)&qbl, g_qbl);
    cudaGetSymbolAddress((void**)&kbh, g_kbh); cudaGetSymbolAddress((void**)&kbl, g_kbl);
    cudaGetSymbolAddress((void**)&vbh, g_vbh); cudaGetSymbolAddress((void**)&vbl, g_vbl);

    cudaFuncSetAttribute(gemm_mma, cudaFuncAttributeMaxDynamicSharedMemorySize, GSMEM);
    cudaFuncSetAttribute(flash_mma, cudaFuncAttributeMaxDynamicSharedMemorySize, FSMEM);

    const int nx4 = BT * HIDDEN / 4;        // 2097152
    const int nw4 = HIDDEN * HIDDEN / 4;    // 1048576

    split_bf16<<<nx4 / 256, 256>>>(x,  xh,  xl,  nx4);
    split_bf16<<<nw4 / 256, 256>>>(Wq, wqh, wql, nw4);
    split_bf16<<<nw4 / 256, 256>>>(Wk, wkh, wkl, nw4);
    split_bf16<<<nw4 / 256, 256>>>(Wv, wvh, wvl, nw4);
    split_bf16<<<nw4 / 256, 256>>>(Wo, woh, wol, nw4);

    dim3 gg(HIDDEN / 128, BT / 128);   // (16, 32)
    gemm_mma<<<gg, 256, GSMEM>>>(xh, xl, wqh, wql, qp, HIDDEN, HIDDEN, 1);
    gemm_mma<<<gg, 256, GSMEM>>>(xh, xl, wkh, wkl, kp, HIDDEN, HIDDEN, 1);
    gemm_mma<<<gg, 256, GSMEM>>>(xh, xl, wvh, wvl, vp, HIDDEN, HIDDEN, 1);

    rope_split<<<(BATCH * NHEADS * SEQ * 64) / 256, 256>>>(qp, kp, qbh, qbl, kbh, kbl);
    split_bf16<<<nx4 / 256, 256>>>(vp, vbh, vbl, nx4);

    flash_mma<<<dim3(SEQ / 128, BATCH * NHEADS), 256, FSMEM>>>(qbh, qbl, kbh, kbl,
                                                               vbh, vbl, ap);

    split_bf16<<<nx4 / 256, 256>>>(ap, ah, al, nx4);
    gemm_mma<<<gg, 256, GSMEM>>>(ah, al, woh, wol, out, HIDDEN, HIDDEN, 0);
}

// round 14
// speedup vs baseline: 2.1290x; 1.1184x over previous
#include <cuda_runtime.h>
#include <cuda_bf16.h>
#include <math.h>
#include <stdint.h>

#define HIDDEN 2048
#define NHEADS 16
#define HDIM   128
#define BATCH  2
#define SEQ    2048
#define BT     (BATCH*SEQ)   // 4096

// ---------------- scratch (static device arrays: no allocation) ----------------
__device__ float g_q[(size_t)BATCH*NHEADS*SEQ*HDIM];     // [B,H,T,D] fp32 (pre-rope)
__device__ float g_k[(size_t)BATCH*NHEADS*SEQ*HDIM];

__device__ __nv_bfloat16 g_xh[(size_t)BT*HIDDEN],  g_xl[(size_t)BT*HIDDEN];
__device__ __nv_bfloat16 g_ah[(size_t)BT*HIDDEN],  g_al[(size_t)BT*HIDDEN];
__device__ __nv_bfloat16 g_wqh[(size_t)HIDDEN*HIDDEN], g_wql[(size_t)HIDDEN*HIDDEN];
__device__ __nv_bfloat16 g_wkh[(size_t)HIDDEN*HIDDEN], g_wkl[(size_t)HIDDEN*HIDDEN];
__device__ __nv_bfloat16 g_wvh[(size_t)HIDDEN*HIDDEN], g_wvl[(size_t)HIDDEN*HIDDEN];
__device__ __nv_bfloat16 g_woh[(size_t)HIDDEN*HIDDEN], g_wol[(size_t)HIDDEN*HIDDEN];

// bf16 hi/lo splits of roped Q/K and V, layout [B,H,T,D]
__device__ __nv_bfloat16 g_qbh[(size_t)BT*HIDDEN], g_qbl[(size_t)BT*HIDDEN];
__device__ __nv_bfloat16 g_kbh[(size_t)BT*HIDDEN], g_kbl[(size_t)BT*HIDDEN];
__device__ __nv_bfloat16 g_vbh[(size_t)BT*HIDDEN], g_vbl[(size_t)BT*HIDDEN];

// ======================= portable PTX helpers (sm_80+ ISA only) =======================
__device__ __forceinline__ uint32_t smem_u32(const void* p) {
    uint32_t a;
    asm("{ .reg .u64 t; cvta.to.shared.u64 t, %1; cvt.u32.u64 %0, t; }"
        : "=r"(a) : "l"(p));
    return a;
}

#define CP_ASYNC16(smaddr, gaddr) \
    asm volatile("cp.async.cg.shared.global [%0], [%1], 16;" \
        :: "r"(smaddr), "l"(gaddr))
#define CP_COMMIT() asm volatile("cp.async.commit_group;" ::: "memory")
#define CP_WAIT0()  asm volatile("cp.async.wait_group 0;"  ::: "memory")
#define CP_WAIT1()  asm volatile("cp.async.wait_group 1;"  ::: "memory")

#define LDMATRIX_X4(r0, r1, r2, r3, addr) \
    asm volatile("ldmatrix.sync.aligned.m8n8.x4.shared.b16 {%0,%1,%2,%3}, [%4];" \
        : "=r"(r0), "=r"(r1), "=r"(r2), "=r"(r3) : "r"(addr))

#define LDMATRIX_X4_T(r0, r1, r2, r3, addr) \
    asm volatile("ldmatrix.sync.aligned.m8n8.x4.trans.shared.b16 {%0,%1,%2,%3}, [%4];" \
        : "=r"(r0), "=r"(r1), "=r"(r2), "=r"(r3) : "r"(addr))

#define MMA_BF16(d, a, b) \
    asm volatile( \
        "mma.sync.aligned.m16n8k16.row.col.f32.bf16.bf16.f32 " \
        "{%0,%1,%2,%3}, {%4,%5,%6,%7}, {%8,%9}, {%0,%1,%2,%3};" \
        : "+f"((d)[0]), "+f"((d)[1]), "+f"((d)[2]), "+f"((d)[3]) \
        : "r"((a)[0]), "r"((a)[1]), "r"((a)[2]), "r"((a)[3]), \
          "r"((b)[0]), "r"((b)[1]))

__device__ __forceinline__ void split2_bf16(float a, float b, uint32_t& hi, uint32_t& lo) {
    __nv_bfloat16 ha = __float2bfloat16(a), hb = __float2bfloat16(b);
    __nv_bfloat162 hv, lv;
    hv.x = ha; hv.y = hb;
    lv.x = __float2bfloat16(a - __bfloat162float(ha));
    lv.y = __float2bfloat16(b - __bfloat162float(hb));
    hi = *reinterpret_cast<uint32_t*>(&hv);
    lo = *reinterpret_cast<uint32_t*>(&lv);
}

// =================================================================================
// split fp32 -> bf16 hi + bf16 lo  (a = hi + lo + O(2^-18 a))
// =================================================================================
__global__ void split_bf16(const float* __restrict__ s, __nv_bfloat16* __restrict__ h,
                           __nv_bfloat16* __restrict__ l, int n4)
{
    int i = blockIdx.x * blockDim.x + threadIdx.x;
    if (i >= n4) return;
    float4 a = ((const float4*)s)[i];
    uint32_t h0, l0, h1, l1;
    split2_bf16(a.x, a.y, h0, l0);
    split2_bf16(a.z, a.w, h1, l1);
    ((uint32_t*)h)[i * 2]     = h0;
    ((uint32_t*)h)[i * 2 + 1] = h1;
    ((uint32_t*)l)[i * 2]     = l0;
    ((uint32_t*)l)[i * 2 + 1] = l1;
}

// 4 weight matrices in one launch (blockIdx.y selects)
__global__ void split_bf16_w4(const float* __restrict__ s0, const float* __restrict__ s1,
                              const float* __restrict__ s2, const float* __restrict__ s3,
                              __nv_bfloat16* __restrict__ h0p, __nv_bfloat16* __restrict__ l0p,
                              __nv_bfloat16* __restrict__ h1p, __nv_bfloat16* __restrict__ l1p,
                              __nv_bfloat16* __restrict__ h2p, __nv_bfloat16* __restrict__ l2p,
                              __nv_bfloat16* __restrict__ h3p, __nv_bfloat16* __restrict__ l3p,
                              int n4)
{
    int i = blockIdx.x * blockDim.x + threadIdx.x;
    if (i >= n4) return;
    const float* s;
    __nv_bfloat16 *h, *l;
    switch (blockIdx.y) {
        case 0:  s = s0; h = h0p; l = l0p; break;
        case 1:  s = s1; h = h1p; l = l1p; break;
        case 2:  s = s2; h = h2p; l = l2p; break;
        default: s = s3; h = h3p; l = l3p; break;
    }
    float4 a = ((const float4*)s)[i];
    uint32_t hx, lx, hy, ly;
    split2_bf16(a.x, a.y, hx, lx);
    split2_bf16(a.z, a.w, hy, ly);
    ((uint32_t*)h)[i * 2]     = hx;
    ((uint32_t*)h)[i * 2 + 1] = hy;
    ((uint32_t*)l)[i * 2]     = lx;
    ((uint32_t*)l)[i * 2 + 1] = ly;
}

// =================================================================================
// HMMA GEMM:  C[M,N] = A[M,K] * B[N,K]^T, bf16x3 emulated fp32.
// CTA tile 128x128, 8 warps (4 M x 2 N), K-chunk 32 bf16,
// 2-stage cp.async double buffer (wait_group 1), 2 CTAs/SM.
// mode 0: C fp32 row-major [M,N]
// mode 1: C fp32 scatter to [B,H,T,D]
// mode 2: Ch/Cl bf16 hi/lo scatter to [B,H,T,D]  (fused output split)
// =================================================================================
#define GPB    80                 // smem row pitch bytes
#define GTILE  (128 * GPB)        // 10240 B per tile
#define GSTAGE (4 * GTILE)        // Ah, Al, Bh, Bl  = 40960 B
#define GSMEM  (2 * GSTAGE)       // 81920 B -> 2 CTAs/SM

__device__ __forceinline__ void gemm_load_stage(
    uint32_t sbase, int buf,
    const __nv_bfloat16* __restrict__ Ah, const __nv_bfloat16* __restrict__ Al,
    const __nv_bfloat16* __restrict__ Bh, const __nv_bfloat16* __restrict__ Bl,
    int aRow0, int bRow0, int koff, int K, int tid)
{
    const uint32_t sb = sbase + buf * GSTAGE;
    #pragma unroll
    for (int it = 0; it < 2; it++) {
        const int q   = tid + it * 256;      // 0..511
        const int row = q >> 2;              // 0..127
        const int kc  = q & 3;               // 16B chunk in row
        const uint32_t so = row * GPB + kc * 16;
        const size_t ga = (size_t)(aRow0 + row) * K + koff + kc * 8;
        const size_t gb = (size_t)(bRow0 + row) * K + koff + kc * 8;
        CP_ASYNC16(sb + so,             (const void*)(Ah + ga));
        CP_ASYNC16(sb + GTILE + so,     (const void*)(Al + ga));
        CP_ASYNC16(sb + 2 * GTILE + so, (const void*)(Bh + gb));
        CP_ASYNC16(sb + 3 * GTILE + so, (const void*)(Bl + gb));
    }
}

__global__ void __launch_bounds__(256, 2)
gemm_mma(const __nv_bfloat16* __restrict__ Ah, const __nv_bfloat16* __restrict__ Al,
         const __nv_bfloat16* __restrict__ Bh, const __nv_bfloat16* __restrict__ Bl,
         float* __restrict__ C,
         __nv_bfloat16* __restrict__ Ch, __nv_bfloat16* __restrict__ Cl,
         int K, int N, int mode)
{
    extern __shared__ char sm[];
    const uint32_t sbase = smem_u32(sm);
    const int tid  = threadIdx.x;
    const int wid  = tid >> 5;
    const int lane = tid & 31;
    const int wm   = wid & 3;
    const int wn   = wid >> 2;
    const int bn   = blockIdx.x;
    const int bm   = blockIdx.y;
    const int aRow0 = bm * 128;
    const int bRow0 = bn * 128;
    const int NKC   = K >> 5;

    float acc[2][8][4];
    #pragma unroll
    for (int mt = 0; mt < 2; mt++)
        #pragma unroll
        for (int nt = 0; nt < 8; nt++)
            #pragma unroll
            for (int e = 0; e < 4; e++) acc[mt][nt][e] = 0.0f;

    const uint32_t lrow = lane & 15;
    const uint32_t lkh  = (lane >> 4) * 16;

    // preload stages 0, 1
    gemm_load_stage(sbase, 0, Ah, Al, Bh, Bl, aRow0, bRow0, 0,  K, tid); CP_COMMIT();
    gemm_load_stage(sbase, 1, Ah, Al, Bh, Bl, aRow0, bRow0, 32, K, tid); CP_COMMIT();

    for (int c = 0; c < NKC; c++) {
        if (c + 1 < NKC) { CP_WAIT1(); } else { CP_WAIT0(); }
        __syncthreads();

        const uint32_t abase = sbase + (c & 1) * GSTAGE;
        const uint32_t bbase = abase + 2 * GTILE;

        #pragma unroll
        for (int kk = 0; kk < 2; kk++) {
            const uint32_t ksel = kk * 32 + lkh;
            uint32_t ah_[2][4], al_[2][4];
            #pragma unroll
            for (int mt = 0; mt < 2; mt++) {
                const uint32_t ra = abase + (wm * 32 + mt * 16 + lrow) * GPB + ksel;
                LDMATRIX_X4(ah_[mt][0], ah_[mt][1], ah_[mt][2], ah_[mt][3], ra);
                LDMATRIX_X4(al_[mt][0], al_[mt][1], al_[mt][2], al_[mt][3], ra + GTILE);
            }
            #pragma unroll
            for (int p = 0; p < 4; p++) {   // one B group live at a time (reg pressure)
                const uint32_t rb = bbase + (wn * 64 + p * 16 + lrow) * GPB + ksel;
                uint32_t t0, t1, t2, t3;
                uint32_t bh0[2], bh1[2], bl0[2], bl1[2];
                LDMATRIX_X4(t0, t1, t2, t3, rb);
                bh0[0] = t0; bh0[1] = t2; bh1[0] = t1; bh1[1] = t3;
                LDMATRIX_X4(t0, t1, t2, t3, rb + GTILE);
                bl0[0] = t0; bl0[1] = t2; bl1[0] = t1; bl1[1] = t3;
                #pragma unroll
                for (int mt = 0; mt < 2; mt++) {
                    MMA_BF16(acc[mt][2*p],   ah_[mt], bh0);
                    MMA_BF16(acc[mt][2*p],   ah_[mt], bl0);
                    MMA_BF16(acc[mt][2*p],   al_[mt], bh0);
                    MMA_BF16(acc[mt][2*p+1], ah_[mt], bh1);
                    MMA_BF16(acc[mt][2*p+1], ah_[mt], bl1);
                    MMA_BF16(acc[mt][2*p+1], al_[mt], bh1);
                }
            }
        }

        __syncthreads();    // all reads of buffer (c&1) done before re-fill
        if (c + 2 < NKC) {
            gemm_load_stage(sbase, c & 1, Ah, Al, Bh, Bl,
                            aRow0, bRow0, (c + 2) * 32, K, tid);
            CP_COMMIT();
        }
    }

    // ---- epilogue ----
    const int tr = lane >> 2;
    const int tc = (lane & 3) * 2;
    #pragma unroll
    for (int mt = 0; mt < 2; mt++) {
        #pragma unroll
        for (int rr = 0; rr < 2; rr++) {
            const int m = aRow0 + wm * 32 + mt * 16 + rr * 8 + tr;
            size_t base;
            if (mode == 0) {
                base = (size_t)m * N + bn * 128;
            } else {
                const int bb = m >> 11;
                const int t  = m & 2047;
                base = (((size_t)(bb * NHEADS + bn)) * SEQ + t) << 7;
            }
            if (mode == 2) {
                #pragma unroll
                for (int nt = 0; nt < 8; nt++) {
                    uint32_t hi, lo;
                    split2_bf16(acc[mt][nt][rr * 2 + 0], acc[mt][nt][rr * 2 + 1], hi, lo);
                    const size_t idx = base + wn * 64 + nt * 8 + tc;
                    *(uint32_t*)(Ch + idx) = hi;
                    *(uint32_t*)(Cl + idx) = lo;
                }
            } else {
                float* dst = C + base;
                #pragma unroll
                for (int nt = 0; nt < 8; nt++) {
                    float2 v;
                    v.x = acc[mt][nt][rr * 2 + 0];
                    v.y = acc[mt][nt][rr * 2 + 1];
                    *(float2*)(dst + wn * 64 + nt * 8 + tc) = v;
                }
            }
        }
    }
}

// =================================================================================
// RoPE + split: reads fp32 q,k [B,H,T,D], writes bf16 hi/lo splits.
// =================================================================================
__global__ void rope_split(const float* __restrict__ q, const float* __restrict__ k,
                           __nv_bfloat16* __restrict__ qbh, __nv_bfloat16* __restrict__ qbl,
                           __nv_bfloat16* __restrict__ kbh, __nv_bfloat16* __restrict__ kbl)
{
    const int idx = blockIdx.x * blockDim.x + threadIdx.x;
    const int i   = idx & 63;
    const int row = idx >> 6;
    const int t   = row & (SEQ - 1);

    const float inv = exp2f(-(float)i * 0.20762050593046014f);  // 10000^(-i/64)
    const float ang = (float)t * inv;
    float s, c;
    sincosf(ang, &s, &c);

    const size_t base = (size_t)row * HDIM;
    const float q1 = q[base + i], q2 = q[base + i + 64];
    const float k1 = k[base + i], k2 = k[base + i + 64];
    const float qa = q1 * c - q2 * s, qb = q2 * c + q1 * s;
    const float ka = k1 * c - k2 * s, kb = k2 * c + k1 * s;

    __nv_bfloat16 h;
    h = __float2bfloat16(qa); qbh[base + i]      = h; qbl[base + i]      = __float2bfloat16(qa - __bfloat162float(h));
    h = __float2bfloat16(qb); qbh[base + i + 64] = h; qbl[base + i + 64] = __float2bfloat16(qb - __bfloat162float(h));
    h = __float2bfloat16(ka); kbh[base + i]      = h; kbl[base + i]      = __float2bfloat16(ka - __bfloat162float(h));
    h = __float2bfloat16(kb); kbh[base + i + 64] = h; kbl[base + i + 64] = __float2bfloat16(kb - __bfloat162float(h));
}

// =================================================================================
// HMMA flash attention, causal, bf16x3. BM=128 (8 warps x 16 rows), BN=64, D=128.
// Double-buffered K/V stages (cp.async). Output: bf16 hi/lo splits [B,T,C].
// =================================================================================
#define FPB      272                  // smem row pitch bytes (136 bf16)
#define FQ_TILE  (128 * FPB)          // 34816
#define FKV_TILE (64 * FPB)           // 17408
#define FSM_KV(s) (2 * FQ_TILE + (s) * (4 * FKV_TILE))
#define FSMEM    (2 * FQ_TILE + 2 * 4 * FKV_TILE)   // 208896

__device__ __forceinline__ void fa_load_kv(
    uint32_t sbase, int s,
    const __nv_bfloat16* __restrict__ kh, const __nv_bfloat16* __restrict__ kl,
    const __nv_bfloat16* __restrict__ vh, const __nv_bfloat16* __restrict__ vl,
    size_t off, int tid)
{
    const uint32_t sb = sbase + FSM_KV(s);
    #pragma unroll
    for (int it = 0; it < 4; it++) {
        const int q   = tid + it * 256;   // 0..1023
        const int row = q >> 4;           // 0..63
        const int ck  = q & 15;
        const uint32_t so = row * FPB + ck * 16;
        const size_t go = off + (size_t)row * HDIM + ck * 8;
        CP_ASYNC16(sb + so,                (const void*)(kh + go));
        CP_ASYNC16(sb + FKV_TILE + so,     (const void*)(kl + go));
        CP_ASYNC16(sb + 2 * FKV_TILE + so, (const void*)(vh + go));
        CP_ASYNC16(sb + 3 * FKV_TILE + so, (const void*)(vl + go));
    }
}

__global__ void __launch_bounds__(256, 1)
flash_mma(const __nv_bfloat16* __restrict__ qh, const __nv_bfloat16* __restrict__ ql,
          const __nv_bfloat16* __restrict__ kh, const __nv_bfloat16* __restrict__ kl,
          const __nv_bfloat16* __restrict__ vh, const __nv_bfloat16* __restrict__ vl,
          __nv_bfloat16* __restrict__ oh, __nv_bfloat16* __restrict__ ol)
{
    extern __shared__ char sm[];
    const uint32_t sbase = smem_u32(sm);
    const int tid  = threadIdx.x;
    const int wid  = tid >> 5;
    const int lane = tid & 31;
    const int bh   = blockIdx.y;
    const int qi   = (gridDim.x - 1) - blockIdx.x;   // heavy q-tiles first
    const float scale = 0.08838834764831845f;        // 1/sqrt(128)

    // ---- load Q hi/lo into smem ----
    const size_t qoff = ((size_t)bh * SEQ + (size_t)qi * 128) * HDIM;
    for (int idx = tid; idx < 128 * 16; idx += 256) {
        const int row = idx >> 4, ck = idx & 15;
        const uint32_t so = row * FPB + ck * 16;
        *(uint4*)(sm + so)           = *(const uint4*)(qh + qoff + (size_t)row * HDIM + ck * 8);
        *(uint4*)(sm + FQ_TILE + so) = *(const uint4*)(ql + qoff + (size_t)row * HDIM + ck * 8);
    }

    const int nkv = 2 * qi + 2;
    const size_t bhoff = (size_t)bh * SEQ * HDIM;
    fa_load_kv(sbase, 0, kh, kl, vh, vl, bhoff, tid);               CP_COMMIT();
    fa_load_kv(sbase, 1, kh, kl, vh, vl, bhoff + 64 * HDIM, tid);   CP_COMMIT();

    float oacc[16][4];
    #pragma unroll
    for (int nt = 0; nt < 16; nt++)
        #pragma unroll
        for (int e = 0; e < 4; e++) oacc[nt][e] = 0.0f;
    float m1 = -1e30f, m2 = -1e30f, l1 = 0.0f, l2 = 0.0f;

    const int r1 = lane >> 2;            // 0..7
    const int c2 = (lane & 3) * 2;
    const uint32_t qrow = sbase + (wid * 16 + (lane & 15)) * FPB + (lane >> 4) * 16;
    const uint32_t lrow_off = (lane & 15) * FPB + (lane >> 4) * 16;

    for (int j = 0; j < nkv; j++) {
        if (j + 1 < nkv) { CP_WAIT1(); } else { CP_WAIT0(); }
        __syncthreads();

        const uint32_t kvb = sbase + FSM_KV(j & 1);
        const bool active = (j * 64 <= qi * 128 + wid * 16 + 15);
        if (active) {
            // ---- S = Q K^T (3-term bf16) ----
            float sacc[8][4];
            #pragma unroll
            for (int nt = 0; nt < 8; nt++)
                #pragma unroll
                for (int e = 0; e < 4; e++) sacc[nt][e] = 0.0f;

            const uint32_t krow = kvb + lrow_off;
            #pragma unroll
            for (int kd = 0; kd < 8; kd++) {
                uint32_t ah4[4], al4[4];
                LDMATRIX_X4(ah4[0], ah4[1], ah4[2], ah4[3], qrow + kd * 32);
                LDMATRIX_X4(al4[0], al4[1], al4[2], al4[3], qrow + FQ_TILE + kd * 32);
                #pragma unroll
                for (int p = 0; p < 4; p++) {
                    uint32_t t0, t1, t2, t3;
                    uint32_t bhf[2][2], blf[2][2];
                    LDMATRIX_X4(t0, t1, t2, t3, krow + p * (16 * FPB) + kd * 32);
                    bhf[0][0] = t0; bhf[0][1] = t2; bhf[1][0] = t1; bhf[1][1] = t3;
                    LDMATRIX_X4(t0, t1, t2, t3, krow + FKV_TILE + p * (16 * FPB) + kd * 32);
                    blf[0][0] = t0; blf[0][1] = t2; blf[1][0] = t1; blf[1][1] = t3;
                    MMA_BF16(sacc[2*p],   ah4, bhf[0]);
                    MMA_BF16(sacc[2*p],   ah4, blf[0]);
                    MMA_BF16(sacc[2*p],   al4, bhf[0]);
                    MMA_BF16(sacc[2*p+1], ah4, bhf[1]);
                    MMA_BF16(sacc[2*p+1], ah4, blf[1]);
                    MMA_BF16(sacc[2*p+1], al4, bhf[1]);
                }
            }

            // ---- scale + causal mask + online softmax ----
            const bool need_mask = (j * 64 + 63 > qi * 128 + wid * 16);
            const int grow1 = qi * 128 + wid * 16 + r1;
            float mx1 = m1, mx2 = m2;
            #pragma unroll
            for (int nt = 0; nt < 8; nt++) {
                #pragma unroll
                for (int e = 0; e < 4; e++) sacc[nt][e] *= scale;
                if (need_mask) {
                    const int col = j * 64 + nt * 8 + c2;
                    if (col     > grow1)     sacc[nt][0] = -1e30f;
                    if (col + 1 > grow1)     sacc[nt][1] = -1e30f;
                    if (col     > grow1 + 8) sacc[nt][2] = -1e30f;
                    if (col + 1 > grow1 + 8) sacc[nt][3] = -1e30f;
                }
                mx1 = fmaxf(mx1, fmaxf(sacc[nt][0], sacc[nt][1]));
                mx2 = fmaxf(mx2, fmaxf(sacc[nt][2], sacc[nt][3]));
            }
            mx1 = fmaxf(mx1, __shfl_xor_sync(0xffffffffu, mx1, 1));
            mx1 = fmaxf(mx1, __shfl_xor_sync(0xffffffffu, mx1, 2));
            mx2 = fmaxf(mx2, __shfl_xor_sync(0xffffffffu, mx2, 1));
            mx2 = fmaxf(mx2, __shfl_xor_sync(0xffffffffu, mx2, 2));

            const float alpha1 = __expf(m1 - mx1);
            const float alpha2 = __expf(m2 - mx2);
            m1 = mx1; m2 = mx2;

            float sum1 = 0.0f, sum2 = 0.0f;
            #pragma unroll
            for (int nt = 0; nt < 8; nt++) {
                sacc[nt][0] = __expf(sacc[nt][0] - mx1);
                sacc[nt][1] = __expf(sacc[nt][1] - mx1);
                sacc[nt][2] = __expf(sacc[nt][2] - mx2);
                sacc[nt][3] = __expf(sacc[nt][3] - mx2);
                sum1 += sacc[nt][0] + sacc[nt][1];
                sum2 += sacc[nt][2] + sacc[nt][3];
            }
            l1 = l1 * alpha1 + sum1;    // per-lane partial; quad-reduced at end
            l2 = l2 * alpha2 + sum2;

            #pragma unroll
            for (int nt = 0; nt < 16; nt++) {
                oacc[nt][0] *= alpha1; oacc[nt][1] *= alpha1;
                oacc[nt][2] *= alpha2; oacc[nt][3] *= alpha2;
            }

            // ---- O += P V (3-term bf16) ----
            const uint32_t vbase = kvb + 2 * FKV_TILE;
            #pragma unroll
            for (int g = 0; g < 4; g++) {
                uint32_t pha[4], pla[4];
                split2_bf16(sacc[2*g][0],   sacc[2*g][1],   pha[0], pla[0]);
                split2_bf16(sacc[2*g][2],   sacc[2*g][3],   pha[1], pla[1]);
                split2_bf16(sacc[2*g+1][0], sacc[2*g+1][1], pha[2], pla[2]);
                split2_bf16(sacc[2*g+1][2], sacc[2*g+1][3], pha[3], pla[3]);

                const uint32_t va = vbase + g * (16 * FPB) + lrow_off;
                #pragma unroll
                for (int pp = 0; pp < 8; pp++) {
                    uint32_t t0, t1, t2, t3;
                    LDMATRIX_X4_T(t0, t1, t2, t3, va + pp * 32);
                    uint32_t vh0[2] = { t0, t1 }, vh1[2] = { t2, t3 };
                    LDMATRIX_X4_T(t0, t1, t2, t3, va + FKV_TILE + pp * 32);
                    uint32_t vl0[2] = { t0, t1 }, vl1[2] = { t2, t3 };
                    MMA_BF16(oacc[2*pp],   pha, vh0);
                    MMA_BF16(oacc[2*pp],   pla, vh0);
                    MMA_BF16(oacc[2*pp],   pha, vl0);
                    MMA_BF16(oacc[2*pp+1], pha, vh1);
                    MMA_BF16(oacc[2*pp+1], pla, vh1);
                    MMA_BF16(oacc[2*pp+1], pha, vl1);
                }
            }
        }
        __syncthreads();    // all reads of stage (j&1) done before overwrite
        if (j + 2 < nkv) {
            fa_load_kv(sbase, j & 1, kh, kl, vh, vl,
                       bhoff + (size_t)(j + 2) * 64 * HDIM, tid);
            CP_COMMIT();
        }
    }

    // ---- finalize: quad-reduce l, normalize, write bf16 hi/lo [B,T,C] ----
    l1 += __shfl_xor_sync(0xffffffffu, l1, 1);
    l1 += __shfl_xor_sync(0xffffffffu, l1, 2);
    l2 += __shfl_xor_sync(0xffffffffu, l2, 1);
    l2 += __shfl_xor_sync(0xffffffffu, l2, 2);
    const float inv1 = 1.0f / l1;
    const float inv2 = 1.0f / l2;

    const int b = bh >> 4;
    const int h = bh & 15;
    const int row1 = qi * 128 + wid * 16 + r1;
    const size_t ob1 = ((size_t)(b * SEQ + row1)) * HIDDEN + h * HDIM;
    const size_t ob2 = ob1 + (size_t)8 * HIDDEN;
    #pragma unroll
    for (int nt = 0; nt < 16; nt++) {
        uint32_t hi, lo;
        split2_bf16(oacc[nt][0] * inv1, oacc[nt][1] * inv1, hi, lo);
        *(uint32_t*)(oh + ob1 + nt * 8 + c2) = hi;
        *(uint32_t*)(ol + ob1 + nt * 8 + c2) = lo;
        split2_bf16(oacc[nt][2] * inv2, oacc[nt][3] * inv2, hi, lo);
        *(uint32_t*)(oh + ob2 + nt * 8 + c2) = hi;
        *(uint32_t*)(ol + ob2 + nt * 8 + c2) = lo;
    }
}

// =================================================================================
// launch
// =================================================================================
extern "C" void kernel_launch(void* const* d_in, const int* in_sizes, int n_in,
                              void* d_out, int out_size)
{
    (void)in_sizes; (void)n_in; (void)out_size;
    const float* x  = (const float*)d_in[0];
    const float* Wq = (const float*)d_in[1];
    const float* Wk = (const float*)d_in[2];
    const float* Wv = (const float*)d_in[3];
    const float* Wo = (const float*)d_in[4];
    float* out = (float*)d_out;

    float *qp, *kp;
    __nv_bfloat16 *xh, *xl, *ah, *al;
    __nv_bfloat16 *wqh, *wql, *wkh, *wkl, *wvh, *wvl, *woh, *wol;
    __nv_bfloat16 *qbh, *qbl, *kbh, *kbl, *vbh, *vbl;
    cudaGetSymbolAddress((void**)&qp, g_q);
    cudaGetSymbolAddress((void**)&kp, g_k);
    cudaGetSymbolAddress((void**)&xh, g_xh);  cudaGetSymbolAddress((void**)&xl, g_xl);
    cudaGetSymbolAddress((void**)&ah, g_ah);  cudaGetSymbolAddress((void**)&al, g_al);
    cudaGetSymbolAddress((void**)&wqh, g_wqh); cudaGetSymbolAddress((void**)&wql, g_wql);
    cudaGetSymbolAddress((void**)&wkh, g_wkh); cudaGetSymbolAddress((void**)&wkl, g_wkl);
    cudaGetSymbolAddress((void**)&wvh, g_wvh); cudaGetSymbolAddress((void**)&wvl, g_wvl);
    cudaGetSymbolAddress((void**)&woh, g_woh); cudaGetSymbolAddress((void**)&wol, g_wol);
    cudaGetSymbolAddress((void**)&qbh, g_qbh); cudaGetSymbolAddress((void**)&qbl, g_qbl);
    cudaGetSymbolAddress((void**)&kbh, g_kbh); cudaGetSymbolAddress((void**)&kbl, g_kbl);
    cudaGetSymbolAddress((void**)&vbh, g_vbh); cudaGetSymbolAddress((void**)&vbl, g_vbl);

    cudaFuncSetAttribute(gemm_mma, cudaFuncAttributeMaxDynamicSharedMemorySize, GSMEM);
    cudaFuncSetAttribute(flash_mma, cudaFuncAttributeMaxDynamicSharedMemorySize, FSMEM);

    const int nx4 = BT * HIDDEN / 4;        // 2097152
    const int nw4 = HIDDEN * HIDDEN / 4;    // 1048576

    split_bf16<<<nx4 / 256, 256>>>(x, xh, xl, nx4);
    split_bf16_w4<<<dim3(nw4 / 256, 4), 256>>>(Wq, Wk, Wv, Wo,
                                               wqh, wql, wkh, wkl,
                                               wvh, wvl, woh, wol, nw4);

    dim3 gg(HIDDEN / 128, BT / 128);   // (16, 32)
    gemm_mma<<<gg, 256, GSMEM>>>(xh, xl, wqh, wql, qp, nullptr, nullptr, HIDDEN, HIDDEN, 1);
    gemm_mma<<<gg, 256, GSMEM>>>(xh, xl, wkh, wkl, kp, nullptr, nullptr, HIDDEN, HIDDEN, 1);
    gemm_mma<<<gg, 256, GSMEM>>>(xh, xl, wvh, wvl, nullptr, vbh, vbl, HIDDEN, HIDDEN, 2);

    rope_split<<<(BATCH * NHEADS * SEQ * 64) / 256, 256>>>(qp, kp, qbh, qbl, kbh, kbl);

    flash_mma<<<dim3(SEQ / 128, BATCH * NHEADS), 256, FSMEM>>>(qbh, qbl, kbh, kbl,
                                                               vbh, vbl, ah, al);

    gemm_mma<<<gg, 256, GSMEM>>>(ah, al, woh, wol, out, nullptr, nullptr, HIDDEN, HIDDEN, 0);
}

// round 15
// speedup vs baseline: 2.3418x; 1.1000x over previous
#include <cuda_runtime.h>
#include <cuda_bf16.h>
#include <math.h>
#include <stdint.h>

#define HIDDEN 2048
#define NHEADS 16
#define HDIM   128
#define BATCH  2
#define SEQ    2048
#define BT     (BATCH*SEQ)   // 4096

// ---------------- scratch (static device arrays: no allocation) ----------------
__device__ float g_q[(size_t)BATCH*NHEADS*SEQ*HDIM];     // [B,H,T,D] fp32 (pre-rope)
__device__ float g_k[(size_t)BATCH*NHEADS*SEQ*HDIM];

__device__ __nv_bfloat16 g_xh[(size_t)BT*HIDDEN],  g_xl[(size_t)BT*HIDDEN];
__device__ __nv_bfloat16 g_ah[(size_t)BT*HIDDEN],  g_al[(size_t)BT*HIDDEN];
__device__ __nv_bfloat16 g_wqh[(size_t)HIDDEN*HIDDEN], g_wql[(size_t)HIDDEN*HIDDEN];
__device__ __nv_bfloat16 g_wkh[(size_t)HIDDEN*HIDDEN], g_wkl[(size_t)HIDDEN*HIDDEN];
__device__ __nv_bfloat16 g_wvh[(size_t)HIDDEN*HIDDEN], g_wvl[(size_t)HIDDEN*HIDDEN];
__device__ __nv_bfloat16 g_woh[(size_t)HIDDEN*HIDDEN], g_wol[(size_t)HIDDEN*HIDDEN];

// bf16 hi/lo splits of roped Q/K and V, layout [B,H,T,D]
__device__ __nv_bfloat16 g_qbh[(size_t)BT*HIDDEN], g_qbl[(size_t)BT*HIDDEN];
__device__ __nv_bfloat16 g_kbh[(size_t)BT*HIDDEN], g_kbl[(size_t)BT*HIDDEN];
__device__ __nv_bfloat16 g_vbh[(size_t)BT*HIDDEN], g_vbl[(size_t)BT*HIDDEN];

// ======================= portable PTX helpers (sm_80+ ISA only) =======================
__device__ __forceinline__ uint32_t smem_u32(const void* p) {
    uint32_t a;
    asm("{ .reg .u64 t; cvta.to.shared.u64 t, %1; cvt.u32.u64 %0, t; }"
        : "=r"(a) : "l"(p));
    return a;
}

#define CP_ASYNC16(smaddr, gaddr) \
    asm volatile("cp.async.cg.shared.global [%0], [%1], 16;" \
        :: "r"(smaddr), "l"(gaddr))
#define CP_COMMIT() asm volatile("cp.async.commit_group;" ::: "memory")
#define CP_WAIT0()  asm volatile("cp.async.wait_group 0;"  ::: "memory")
#define CP_WAIT1()  asm volatile("cp.async.wait_group 1;"  ::: "memory")

#define LDMATRIX_X4(r0, r1, r2, r3, addr) \
    asm volatile("ldmatrix.sync.aligned.m8n8.x4.shared.b16 {%0,%1,%2,%3}, [%4];" \
        : "=r"(r0), "=r"(r1), "=r"(r2), "=r"(r3) : "r"(addr))

#define LDMATRIX_X4_T(r0, r1, r2, r3, addr) \
    asm volatile("ldmatrix.sync.aligned.m8n8.x4.trans.shared.b16 {%0,%1,%2,%3}, [%4];" \
        : "=r"(r0), "=r"(r1), "=r"(r2), "=r"(r3) : "r"(addr))

#define MMA_BF16(d, a, b) \
    asm volatile( \
        "mma.sync.aligned.m16n8k16.row.col.f32.bf16.bf16.f32 " \
        "{%0,%1,%2,%3}, {%4,%5,%6,%7}, {%8,%9}, {%0,%1,%2,%3};" \
        : "+f"((d)[0]), "+f"((d)[1]), "+f"((d)[2]), "+f"((d)[3]) \
        : "r"((a)[0]), "r"((a)[1]), "r"((a)[2]), "r"((a)[3]), \
          "r"((b)[0]), "r"((b)[1]))

__device__ __forceinline__ void split2_bf16(float a, float b, uint32_t& hi, uint32_t& lo) {
    __nv_bfloat16 ha = __float2bfloat16(a), hb = __float2bfloat16(b);
    __nv_bfloat162 hv, lv;
    hv.x = ha; hv.y = hb;
    lv.x = __float2bfloat16(a - __bfloat162float(ha));
    lv.y = __float2bfloat16(b - __bfloat162float(hb));
    hi = *reinterpret_cast<uint32_t*>(&hv);
    lo = *reinterpret_cast<uint32_t*>(&lv);
}

// =================================================================================
// split fp32 -> bf16 hi + bf16 lo  (a = hi + lo + O(2^-18 a))
// =================================================================================
__global__ void split_bf16(const float* __restrict__ s, __nv_bfloat16* __restrict__ h,
                           __nv_bfloat16* __restrict__ l, int n4)
{
    int i = blockIdx.x * blockDim.x + threadIdx.x;
    if (i >= n4) return;
    float4 a = ((const float4*)s)[i];
    uint32_t h0, l0, h1, l1;
    split2_bf16(a.x, a.y, h0, l0);
    split2_bf16(a.z, a.w, h1, l1);
    ((uint32_t*)h)[i * 2]     = h0;
    ((uint32_t*)h)[i * 2 + 1] = h1;
    ((uint32_t*)l)[i * 2]     = l0;
    ((uint32_t*)l)[i * 2 + 1] = l1;
}

// 4 weight matrices in one launch (blockIdx.y selects)
__global__ void split_bf16_w4(const float* __restrict__ s0, const float* __restrict__ s1,
                              const float* __restrict__ s2, const float* __restrict__ s3,
                              __nv_bfloat16* __restrict__ h0p, __nv_bfloat16* __restrict__ l0p,
                              __nv_bfloat16* __restrict__ h1p, __nv_bfloat16* __restrict__ l1p,
                              __nv_bfloat16* __restrict__ h2p, __nv_bfloat16* __restrict__ l2p,
                              __nv_bfloat16* __restrict__ h3p, __nv_bfloat16* __restrict__ l3p,
                              int n4)
{
    int i = blockIdx.x * blockDim.x + threadIdx.x;
    if (i >= n4) return;
    const float* s;
    __nv_bfloat16 *h, *l;
    switch (blockIdx.y) {
        case 0:  s = s0; h = h0p; l = l0p; break;
        case 1:  s = s1; h = h1p; l = l1p; break;
        case 2:  s = s2; h = h2p; l = l2p; break;
        default: s = s3; h = h3p; l = l3p; break;
    }
    float4 a = ((const float4*)s)[i];
    uint32_t hx, lx, hy, ly;
    split2_bf16(a.x, a.y, hx, lx);
    split2_bf16(a.z, a.w, hy, ly);
    ((uint32_t*)h)[i * 2]     = hx;
    ((uint32_t*)h)[i * 2 + 1] = hy;
    ((uint32_t*)l)[i * 2]     = lx;
    ((uint32_t*)l)[i * 2 + 1] = ly;
}

// =================================================================================
// HMMA GEMM v2:  C[M,N] = A[M,K] * B[N,K]^T, bf16x3 emulated fp32.
// CTA tile 128x128, 8 warps (4 M x 2 N), K-chunk 32 bf16.
// Swizzled 64B-pitch smem (conflict-free, no padding), 3-stage cp.async pipeline,
// ONE __syncthreads per chunk, B fragments double-buffered in registers.
// mode 0: C fp32 row-major [M,N]
// mode 1: C fp32 scatter to [B,H,T,D]
// mode 2: Ch/Cl bf16 hi/lo scatter to [B,H,T,D]  (fused output split)
// =================================================================================
#define GTILE2  8192               // 128 rows x 64 B
#define GSTAGE2 (4 * GTILE2)       // Ah, Al, Bh, Bl = 32768 B
#define GSMEM2  (3 * GSTAGE2)      // 98304 B -> 2 CTAs/SM

// smem offset for (row, 16B-chunk kc) with XOR swizzle
#define GSWZ(row, kc) ((uint32_t)((row) * 64 + ((((kc) ^ (((row) >> 1) & 3))) << 4)))

__device__ __forceinline__ void gemm_load_stage2(
    uint32_t sbase, int buf,
    const __nv_bfloat16* __restrict__ Ah, const __nv_bfloat16* __restrict__ Al,
    const __nv_bfloat16* __restrict__ Bh, const __nv_bfloat16* __restrict__ Bl,
    int aRow0, int bRow0, int koff, int K, int tid)
{
    const uint32_t sb = sbase + buf * GSTAGE2;
    const int idx0 = tid;            // 0..255
    const int idx1 = tid + 256;      // 256..511
    const int row0 = idx0 >> 2, kc0 = idx0 & 3;
    const int row1 = idx1 >> 2, kc1 = idx1 & 3;
    const uint32_t so0 = GSWZ(row0, kc0);
    const uint32_t so1 = GSWZ(row1, kc1);
    const size_t ga0 = (size_t)(aRow0 + row0) * K + koff + kc0 * 8;
    const size_t ga1 = (size_t)(aRow0 + row1) * K + koff + kc1 * 8;
    const size_t gb0 = (size_t)(bRow0 + row0) * K + koff + kc0 * 8;
    const size_t gb1 = (size_t)(bRow0 + row1) * K + koff + kc1 * 8;
    CP_ASYNC16(sb + so0,              (const void*)(Ah + ga0));
    CP_ASYNC16(sb + so1,              (const void*)(Ah + ga1));
    CP_ASYNC16(sb + GTILE2 + so0,     (const void*)(Al + ga0));
    CP_ASYNC16(sb + GTILE2 + so1,     (const void*)(Al + ga1));
    CP_ASYNC16(sb + 2 * GTILE2 + so0, (const void*)(Bh + gb0));
    CP_ASYNC16(sb + 2 * GTILE2 + so1, (const void*)(Bh + gb1));
    CP_ASYNC16(sb + 3 * GTILE2 + so0, (const void*)(Bl + gb0));
    CP_ASYNC16(sb + 3 * GTILE2 + so1, (const void*)(Bl + gb1));
}

__global__ void __launch_bounds__(256, 2)
gemm_mma(const __nv_bfloat16* __restrict__ Ah, const __nv_bfloat16* __restrict__ Al,
         const __nv_bfloat16* __restrict__ Bh, const __nv_bfloat16* __restrict__ Bl,
         float* __restrict__ C,
         __nv_bfloat16* __restrict__ Ch, __nv_bfloat16* __restrict__ Cl,
         int K, int N, int mode)
{
    extern __shared__ char sm[];
    const uint32_t sbase = smem_u32(sm);
    const int tid  = threadIdx.x;
    const int wid  = tid >> 5;
    const int lane = tid & 31;
    const int wm   = wid & 3;
    const int wn   = wid >> 2;
    const int bn   = blockIdx.x;
    const int bm   = blockIdx.y;
    const int aRow0 = bm * 128;
    const int bRow0 = bn * 128;
    const int NKC   = K >> 5;

    float acc[2][8][4];
    #pragma unroll
    for (int mt = 0; mt < 2; mt++)
        #pragma unroll
        for (int nt = 0; nt < 8; nt++)
            #pragma unroll
            for (int e = 0; e < 4; e++) acc[mt][nt][e] = 0.0f;

    const uint32_t lrow  = lane & 15;
    const uint32_t khalf = lane >> 4;          // 0/1
    const uint32_t swz   = (lrow >> 1) & 3;

    // preload stages 0, 1
    gemm_load_stage2(sbase, 0, Ah, Al, Bh, Bl, aRow0, bRow0, 0,  K, tid); CP_COMMIT();
    gemm_load_stage2(sbase, 1, Ah, Al, Bh, Bl, aRow0, bRow0, 32, K, tid); CP_COMMIT();

    int scur = 0, sld = 2;
    for (int c = 0; c < NKC; c++) {
        if (c + 1 < NKC) { CP_WAIT1(); } else { CP_WAIT0(); }
        __syncthreads();

        // prefetch chunk c+2 into the stage consumed at chunk c-1
        if (c + 2 < NKC) {
            gemm_load_stage2(sbase, sld, Ah, Al, Bh, Bl,
                             aRow0, bRow0, (c + 2) * 32, K, tid);
            CP_COMMIT();
            if (++sld == 3) sld = 0;
        }

        const uint32_t abase = sbase + scur * GSTAGE2;
        const uint32_t bbase = abase + 2 * GTILE2;
        if (++scur == 3) scur = 0;

        #pragma unroll
        for (int kk = 0; kk < 2; kk++) {
            const uint32_t sw16 = (((kk * 2 + khalf) ^ swz) << 4);

            uint32_t ah_[2][4], al_[2][4];
            #pragma unroll
            for (int mt = 0; mt < 2; mt++) {
                const uint32_t ra = abase + ((wm * 32 + mt * 16 + lrow) << 6) + sw16;
                LDMATRIX_X4(ah_[mt][0], ah_[mt][1], ah_[mt][2], ah_[mt][3], ra);
                LDMATRIX_X4(al_[mt][0], al_[mt][1], al_[mt][2], al_[mt][3], ra + GTILE2);
            }

            // B fragments: [buf][bh0,bh1,bl0,bl1][2], double buffered over p
            uint32_t bfr[2][4][2];
            #define LOADB(p, bb) do { \
                const uint32_t rb = bbase + ((wn * 64 + (p) * 16 + lrow) << 6) + sw16; \
                uint32_t t0, t1, t2, t3; \
                LDMATRIX_X4(t0, t1, t2, t3, rb); \
                (bb)[0][0] = t0; (bb)[0][1] = t2; (bb)[1][0] = t1; (bb)[1][1] = t3; \
                LDMATRIX_X4(t0, t1, t2, t3, rb + GTILE2); \
                (bb)[2][0] = t0; (bb)[2][1] = t2; (bb)[3][0] = t1; (bb)[3][1] = t3; \
            } while (0)

            LOADB(0, bfr[0]);
            #pragma unroll
            for (int p = 0; p < 4; p++) {
                if (p < 3) LOADB(p + 1, bfr[(p + 1) & 1]);
                uint32_t (*bc)[2] = bfr[p & 1];
                #pragma unroll
                for (int mt = 0; mt < 2; mt++) {
                    MMA_BF16(acc[mt][2*p],   ah_[mt], bc[0]);
                    MMA_BF16(acc[mt][2*p+1], ah_[mt], bc[1]);
                    MMA_BF16(acc[mt][2*p],   ah_[mt], bc[2]);
                    MMA_BF16(acc[mt][2*p+1], ah_[mt], bc[3]);
                    MMA_BF16(acc[mt][2*p],   al_[mt], bc[0]);
                    MMA_BF16(acc[mt][2*p+1], al_[mt], bc[1]);
                }
            }
            #undef LOADB
        }
    }

    // ---- epilogue ----
    const int tr = lane >> 2;
    const int tc = (lane & 3) * 2;
    #pragma unroll
    for (int mt = 0; mt < 2; mt++) {
        #pragma unroll
        for (int rr = 0; rr < 2; rr++) {
            const int m = aRow0 + wm * 32 + mt * 16 + rr * 8 + tr;
            size_t base;
            if (mode == 0) {
                base = (size_t)m * N + bn * 128;
            } else {
                const int bb = m >> 11;
                const int t  = m & 2047;
                base = (((size_t)(bb * NHEADS + bn)) * SEQ + t) << 7;
            }
            if (mode == 2) {
                #pragma unroll
                for (int nt = 0; nt < 8; nt++) {
                    uint32_t hi, lo;
                    split2_bf16(acc[mt][nt][rr * 2 + 0], acc[mt][nt][rr * 2 + 1], hi, lo);
                    const size_t idx = base + wn * 64 + nt * 8 + tc;
                    *(uint32_t*)(Ch + idx) = hi;
                    *(uint32_t*)(Cl + idx) = lo;
                }
            } else {
                float* dst = C + base;
                #pragma unroll
                for (int nt = 0; nt < 8; nt++) {
                    float2 v;
                    v.x = acc[mt][nt][rr * 2 + 0];
                    v.y = acc[mt][nt][rr * 2 + 1];
                    *(float2*)(dst + wn * 64 + nt * 8 + tc) = v;
                }
            }
        }
    }
}

// =================================================================================
// RoPE + split: reads fp32 q,k [B,H,T,D], writes bf16 hi/lo splits.
// =================================================================================
__global__ void rope_split(const float* __restrict__ q, const float* __restrict__ k,
                           __nv_bfloat16* __restrict__ qbh, __nv_bfloat16* __restrict__ qbl,
                           __nv_bfloat16* __restrict__ kbh, __nv_bfloat16* __restrict__ kbl)
{
    const int idx = blockIdx.x * blockDim.x + threadIdx.x;
    const int i   = idx & 63;
    const int row = idx >> 6;
    const int t   = row & (SEQ - 1);

    const float inv = exp2f(-(float)i * 0.20762050593046014f);  // 10000^(-i/64)
    const float ang = (float)t * inv;
    float s, c;
    sincosf(ang, &s, &c);

    const size_t base = (size_t)row * HDIM;
    const float q1 = q[base + i], q2 = q[base + i + 64];
    const float k1 = k[base + i], k2 = k[base + i + 64];
    const float qa = q1 * c - q2 * s, qb = q2 * c + q1 * s;
    const float ka = k1 * c - k2 * s, kb = k2 * c + k1 * s;

    __nv_bfloat16 h;
    h = __float2bfloat16(qa); qbh[base + i]      = h; qbl[base + i]      = __float2bfloat16(qa - __bfloat162float(h));
    h = __float2bfloat16(qb); qbh[base + i + 64] = h; qbl[base + i + 64] = __float2bfloat16(qb - __bfloat162float(h));
    h = __float2bfloat16(ka); kbh[base + i]      = h; kbl[base + i]      = __float2bfloat16(ka - __bfloat162float(h));
    h = __float2bfloat16(kb); kbh[base + i + 64] = h; kbl[base + i + 64] = __float2bfloat16(kb - __bfloat162float(h));
}

// =================================================================================
// HMMA flash attention, causal, bf16x3. BM=128 (8 warps x 16 rows), BN=64, D=128.
// Double-buffered K/V stages (cp.async). Output: bf16 hi/lo splits [B,T,C].
// =================================================================================
#define FPB      272                  // smem row pitch bytes (136 bf16)
#define FQ_TILE  (128 * FPB)          // 34816
#define FKV_TILE (64 * FPB)           // 17408
#define FSM_KV(s) (2 * FQ_TILE + (s) * (4 * FKV_TILE))
#define FSMEM    (2 * FQ_TILE + 2 * 4 * FKV_TILE)   // 208896

__device__ __forceinline__ void fa_load_kv(
    uint32_t sbase, int s,
    const __nv_bfloat16* __restrict__ kh, const __nv_bfloat16* __restrict__ kl,
    const __nv_bfloat16* __restrict__ vh, const __nv_bfloat16* __restrict__ vl,
    size_t off, int tid)
{
    const uint32_t sb = sbase + FSM_KV(s);
    #pragma unroll
    for (int it = 0; it < 4; it++) {
        const int q   = tid + it * 256;   // 0..1023
        const int row = q >> 4;           // 0..63
        const int ck  = q & 15;
        const uint32_t so = row * FPB + ck * 16;
        const size_t go = off + (size_t)row * HDIM + ck * 8;
        CP_ASYNC16(sb + so,                (const void*)(kh + go));
        CP_ASYNC16(sb + FKV_TILE + so,     (const void*)(kl + go));
        CP_ASYNC16(sb + 2 * FKV_TILE + so, (const void*)(vh + go));
        CP_ASYNC16(sb + 3 * FKV_TILE + so, (const void*)(vl + go));
    }
}

__global__ void __launch_bounds__(256, 1)
flash_mma(const __nv_bfloat16* __restrict__ qh, const __nv_bfloat16* __restrict__ ql,
          const __nv_bfloat16* __restrict__ kh, const __nv_bfloat16* __restrict__ kl,
          const __nv_bfloat16* __restrict__ vh, const __nv_bfloat16* __restrict__ vl,
          __nv_bfloat16* __restrict__ oh, __nv_bfloat16* __restrict__ ol)
{
    extern __shared__ char sm[];
    const uint32_t sbase = smem_u32(sm);
    const int tid  = threadIdx.x;
    const int wid  = tid >> 5;
    const int lane = tid & 31;
    const int bh   = blockIdx.y;
    const int qi   = (gridDim.x - 1) - blockIdx.x;   // heavy q-tiles first
    const float scale = 0.08838834764831845f;        // 1/sqrt(128)

    // ---- load Q hi/lo into smem ----
    const size_t qoff = ((size_t)bh * SEQ + (size_t)qi * 128) * HDIM;
    for (int idx = tid; idx < 128 * 16; idx += 256) {
        const int row = idx >> 4, ck = idx & 15;
        const uint32_t so = row * FPB + ck * 16;
        *(uint4*)(sm + so)           = *(const uint4*)(qh + qoff + (size_t)row * HDIM + ck * 8);
        *(uint4*)(sm + FQ_TILE + so) = *(const uint4*)(ql + qoff + (size_t)row * HDIM + ck * 8);
    }

    const int nkv = 2 * qi + 2;
    const size_t bhoff = (size_t)bh * SEQ * HDIM;
    fa_load_kv(sbase, 0, kh, kl, vh, vl, bhoff, tid);               CP_COMMIT();
    fa_load_kv(sbase, 1, kh, kl, vh, vl, bhoff + 64 * HDIM, tid);   CP_COMMIT();

    float oacc[16][4];
    #pragma unroll
    for (int nt = 0; nt < 16; nt++)
        #pragma unroll
        for (int e = 0; e < 4; e++) oacc[nt][e] = 0.0f;
    float m1 = -1e30f, m2 = -1e30f, l1 = 0.0f, l2 = 0.0f;

    const int r1 = lane >> 2;            // 0..7
    const int c2 = (lane & 3) * 2;
    const uint32_t qrow = sbase + (wid * 16 + (lane & 15)) * FPB + (lane >> 4) * 16;
    const uint32_t lrow_off = (lane & 15) * FPB + (lane >> 4) * 16;

    for (int j = 0; j < nkv; j++) {
        if (j + 1 < nkv) { CP_WAIT1(); } else { CP_WAIT0(); }
        __syncthreads();

        const uint32_t kvb = sbase + FSM_KV(j & 1);
        const bool active = (j * 64 <= qi * 128 + wid * 16 + 15);
        if (active) {
            // ---- S = Q K^T (3-term bf16) ----
            float sacc[8][4];
            #pragma unroll
            for (int nt = 0; nt < 8; nt++)
                #pragma unroll
                for (int e = 0; e < 4; e++) sacc[nt][e] = 0.0f;

            const uint32_t krow = kvb + lrow_off;
            #pragma unroll
            for (int kd = 0; kd < 8; kd++) {
                uint32_t ah4[4], al4[4];
                LDMATRIX_X4(ah4[0], ah4[1], ah4[2], ah4[3], qrow + kd * 32);
                LDMATRIX_X4(al4[0], al4[1], al4[2], al4[3], qrow + FQ_TILE + kd * 32);
                #pragma unroll
                for (int p = 0; p < 4; p++) {
                    uint32_t t0, t1, t2, t3;
                    uint32_t bhf[2][2], blf[2][2];
                    LDMATRIX_X4(t0, t1, t2, t3, krow + p * (16 * FPB) + kd * 32);
                    bhf[0][0] = t0; bhf[0][1] = t2; bhf[1][0] = t1; bhf[1][1] = t3;
                    LDMATRIX_X4(t0, t1, t2, t3, krow + FKV_TILE + p * (16 * FPB) + kd * 32);
                    blf[0][0] = t0; blf[0][1] = t2; blf[1][0] = t1; blf[1][1] = t3;
                    MMA_BF16(sacc[2*p],   ah4, bhf[0]);
                    MMA_BF16(sacc[2*p],   ah4, blf[0]);
                    MMA_BF16(sacc[2*p],   al4, bhf[0]);
                    MMA_BF16(sacc[2*p+1], ah4, bhf[1]);
                    MMA_BF16(sacc[2*p+1], ah4, blf[1]);
                    MMA_BF16(sacc[2*p+1], al4, bhf[1]);
                }
            }

            // ---- scale + causal mask + online softmax ----
            const bool need_mask = (j * 64 + 63 > qi * 128 + wid * 16);
            const int grow1 = qi * 128 + wid * 16 + r1;
            float mx1 = m1, mx2 = m2;
            #pragma unroll
            for (int nt = 0; nt < 8; nt++) {
                #pragma unroll
                for (int e = 0; e < 4; e++) sacc[nt][e] *= scale;
                if (need_mask) {
                    const int col = j * 64 + nt * 8 + c2;
                    if (col     > grow1)     sacc[nt][0] = -1e30f;
                    if (col + 1 > grow1)     sacc[nt][1] = -1e30f;
                    if (col     > grow1 + 8) sacc[nt][2] = -1e30f;
                    if (col + 1 > grow1 + 8) sacc[nt][3] = -1e30f;
                }
                mx1 = fmaxf(mx1, fmaxf(sacc[nt][0], sacc[nt][1]));
                mx2 = fmaxf(mx2, fmaxf(sacc[nt][2], sacc[nt][3]));
            }
            mx1 = fmaxf(mx1, __shfl_xor_sync(0xffffffffu, mx1, 1));
            mx1 = fmaxf(mx1, __shfl_xor_sync(0xffffffffu, mx1, 2));
            mx2 = fmaxf(mx2, __shfl_xor_sync(0xffffffffu, mx2, 1));
            mx2 = fmaxf(mx2, __shfl_xor_sync(0xffffffffu, mx2, 2));

            const float alpha1 = __expf(m1 - mx1);
            const float alpha2 = __expf(m2 - mx2);
            m1 = mx1; m2 = mx2;

            float sum1 = 0.0f, sum2 = 0.0f;
            #pragma unroll
            for (int nt = 0; nt < 8; nt++) {
                sacc[nt][0] = __expf(sacc[nt][0] - mx1);
                sacc[nt][1] = __expf(sacc[nt][1] - mx1);
                sacc[nt][2] = __expf(sacc[nt][2] - mx2);
                sacc[nt][3] = __expf(sacc[nt][3] - mx2);
                sum1 += sacc[nt][0] + sacc[nt][1];
                sum2 += sacc[nt][2] + sacc[nt][3];
            }
            l1 = l1 * alpha1 + sum1;    // per-lane partial; quad-reduced at end
            l2 = l2 * alpha2 + sum2;

            #pragma unroll
            for (int nt = 0; nt < 16; nt++) {
                oacc[nt][0] *= alpha1; oacc[nt][1] *= alpha1;
                oacc[nt][2] *= alpha2; oacc[nt][3] *= alpha2;
            }

            // ---- O += P V (3-term bf16) ----
            const uint32_t vbase = kvb + 2 * FKV_TILE;
            #pragma unroll
            for (int g = 0; g < 4; g++) {
                uint32_t pha[4], pla[4];
                split2_bf16(sacc[2*g][0],   sacc[2*g][1],   pha[0], pla[0]);
                split2_bf16(sacc[2*g][2],   sacc[2*g][3],   pha[1], pla[1]);
                split2_bf16(sacc[2*g+1][0], sacc[2*g+1][1], pha[2], pla[2]);
                split2_bf16(sacc[2*g+1][2], sacc[2*g+1][3], pha[3], pla[3]);

                const uint32_t va = vbase + g * (16 * FPB) + lrow_off;
                #pragma unroll
                for (int pp = 0; pp < 8; pp++) {
                    uint32_t t0, t1, t2, t3;
                    LDMATRIX_X4_T(t0, t1, t2, t3, va + pp * 32);
                    uint32_t vh0[2] = { t0, t1 }, vh1[2] = { t2, t3 };
                    LDMATRIX_X4_T(t0, t1, t2, t3, va + FKV_TILE + pp * 32);
                    uint32_t vl0[2] = { t0, t1 }, vl1[2] = { t2, t3 };
                    MMA_BF16(oacc[2*pp],   pha, vh0);
                    MMA_BF16(oacc[2*pp],   pla, vh0);
                    MMA_BF16(oacc[2*pp],   pha, vl0);
                    MMA_BF16(oacc[2*pp+1], pha, vh1);
                    MMA_BF16(oacc[2*pp+1], pla, vh1);
                    MMA_BF16(oacc[2*pp+1], pha, vl1);
                }
            }
        }
        __syncthreads();    // all reads of stage (j&1) done before overwrite
        if (j + 2 < nkv) {
            fa_load_kv(sbase, j & 1, kh, kl, vh, vl,
                       bhoff + (size_t)(j + 2) * 64 * HDIM, tid);
            CP_COMMIT();
        }
    }

    // ---- finalize: quad-reduce l, normalize, write bf16 hi/lo [B,T,C] ----
    l1 += __shfl_xor_sync(0xffffffffu, l1, 1);
    l1 += __shfl_xor_sync(0xffffffffu, l1, 2);
    l2 += __shfl_xor_sync(0xffffffffu, l2, 1);
    l2 += __shfl_xor_sync(0xffffffffu, l2, 2);
    const float inv1 = 1.0f / l1;
    const float inv2 = 1.0f / l2;

    const int b = bh >> 4;
    const int h = bh & 15;
    const int row1 = qi * 128 + wid * 16 + r1;
    const size_t ob1 = ((size_t)(b * SEQ + row1)) * HIDDEN + h * HDIM;
    const size_t ob2 = ob1 + (size_t)8 * HIDDEN;
    #pragma unroll
    for (int nt = 0; nt < 16; nt++) {
        uint32_t hi, lo;
        split2_bf16(oacc[nt][0] * inv1, oacc[nt][1] * inv1, hi, lo);
        *(uint32_t*)(oh + ob1 + nt * 8 + c2) = hi;
        *(uint32_t*)(ol + ob1 + nt * 8 + c2) = lo;
        split2_bf16(oacc[nt][2] * inv2, oacc[nt][3] * inv2, hi, lo);
        *(uint32_t*)(oh + ob2 + nt * 8 + c2) = hi;
        *(uint32_t*)(ol + ob2 + nt * 8 + c2) = lo;
    }
}

// =================================================================================
// launch
// =================================================================================
extern "C" void kernel_launch(void* const* d_in, const int* in_sizes, int n_in,
                              void* d_out, int out_size)
{
    (void)in_sizes; (void)n_in; (void)out_size;
    const float* x  = (const float*)d_in[0];
    const float* Wq = (const float*)d_in[1];
    const float* Wk = (const float*)d_in[2];
    const float* Wv = (const float*)d_in[3];
    const float* Wo = (const float*)d_in[4];
    float* out = (float*)d_out;

    float *qp, *kp;
    __nv_bfloat16 *xh, *xl, *ah, *al;
    __nv_bfloat16 *wqh, *wql, *wkh, *wkl, *wvh, *wvl, *woh, *wol;
    __nv_bfloat16 *qbh, *qbl, *kbh, *kbl, *vbh, *vbl;
    cudaGetSymbolAddress((void**)&qp, g_q);
    cudaGetSymbolAddress((void**)&kp, g_k);
    cudaGetSymbolAddress((void**)&xh, g_xh);  cudaGetSymbolAddress((void**)&xl, g_xl);
    cudaGetSymbolAddress((void**)&ah, g_ah);  cudaGetSymbolAddress((void**)&al, g_al);
    cudaGetSymbolAddress((void**)&wqh, g_wqh); cudaGetSymbolAddress((void**)&wql, g_wql);
    cudaGetSymbolAddress((void**)&wkh, g_wkh); cudaGetSymbolAddress((void**)&wkl, g_wkl);
    cudaGetSymbolAddress((void**)&wvh, g_wvh); cudaGetSymbolAddress((void**)&wvl, g_wvl);
    cudaGetSymbolAddress((void**)&woh, g_woh); cudaGetSymbolAddress((void**)&wol, g_wol);
    cudaGetSymbolAddress((void**)&qbh, g_qbh); cudaGetSymbolAddress((void**)&qbl, g_qbl);
    cudaGetSymbolAddress((void**)&kbh, g_kbh); cudaGetSymbolAddress((void**)&kbl, g_kbl);
    cudaGetSymbolAddress((void**)&vbh, g_vbh); cudaGetSymbolAddress((void**)&vbl, g_vbl);

    cudaFuncSetAttribute(gemm_mma, cudaFuncAttributeMaxDynamicSharedMemorySize, GSMEM2);
    cudaFuncSetAttribute(flash_mma, cudaFuncAttributeMaxDynamicSharedMemorySize, FSMEM);

    const int nx4 = BT * HIDDEN / 4;        // 2097152
    const int nw4 = HIDDEN * HIDDEN / 4;    // 1048576

    split_bf16<<<nx4 / 256, 256>>>(x, xh, xl, nx4);
    split_bf16_w4<<<dim3(nw4 / 256, 4), 256>>>(Wq, Wk, Wv, Wo,
                                               wqh, wql, wkh, wkl,
                                               wvh, wvl, woh, wol, nw4);

    dim3 gg(HIDDEN / 128, BT / 128);   // (16, 32)
    gemm_mma<<<gg, 256, GSMEM2>>>(xh, xl, wqh, wql, qp, nullptr, nullptr, HIDDEN, HIDDEN, 1);
    gemm_mma<<<gg, 256, GSMEM2>>>(xh, xl, wkh, wkl, kp, nullptr, nullptr, HIDDEN, HIDDEN, 1);
    gemm_mma<<<gg, 256, GSMEM2>>>(xh, xl, wvh, wvl, nullptr, vbh, vbl, HIDDEN, HIDDEN, 2);

    rope_split<<<(BATCH * NHEADS * SEQ * 64) / 256, 256>>>(qp, kp, qbh, qbl, kbh, kbl);

    flash_mma<<<dim3(SEQ / 128, BATCH * NHEADS), 256, FSMEM>>>(qbh, qbl, kbh, kbl,
                                                               vbh, vbl, ah, al);

    gemm_mma<<<gg, 256, GSMEM2>>>(ah, al, woh, wol, out, nullptr, nullptr, HIDDEN, HIDDEN, 0);
}

// round 17
// speedup vs baseline: 2.4577x; 1.0495x over previous
#include <cuda_runtime.h>
#include <cuda_bf16.h>
#include <math.h>
#include <stdint.h>

#define HIDDEN 2048
#define NHEADS 16
#define HDIM   128
#define BATCH  2
#define SEQ    2048
#define BT     (BATCH*SEQ)   // 4096

// ---------------- scratch (static device arrays: no allocation) ----------------
__device__ float g_q[(size_t)BATCH*NHEADS*SEQ*HDIM];     // [B,H,T,D] fp32 (pre-rope)
__device__ float g_k[(size_t)BATCH*NHEADS*SEQ*HDIM];

__device__ __nv_bfloat16 g_xh[(size_t)BT*HIDDEN],  g_xl[(size_t)BT*HIDDEN];
__device__ __nv_bfloat16 g_ah[(size_t)BT*HIDDEN],  g_al[(size_t)BT*HIDDEN];
__device__ __nv_bfloat16 g_wqh[(size_t)HIDDEN*HIDDEN], g_wql[(size_t)HIDDEN*HIDDEN];
__device__ __nv_bfloat16 g_wkh[(size_t)HIDDEN*HIDDEN], g_wkl[(size_t)HIDDEN*HIDDEN];
__device__ __nv_bfloat16 g_wvh[(size_t)HIDDEN*HIDDEN], g_wvl[(size_t)HIDDEN*HIDDEN];
__device__ __nv_bfloat16 g_woh[(size_t)HIDDEN*HIDDEN], g_wol[(size_t)HIDDEN*HIDDEN];

// bf16 hi/lo splits of roped Q/K and V, layout [B,H,T,D]
__device__ __nv_bfloat16 g_qbh[(size_t)BT*HIDDEN], g_qbl[(size_t)BT*HIDDEN];
__device__ __nv_bfloat16 g_kbh[(size_t)BT*HIDDEN], g_kbl[(size_t)BT*HIDDEN];
__device__ __nv_bfloat16 g_vbh[(size_t)BT*HIDDEN], g_vbl[(size_t)BT*HIDDEN];

// ======================= portable PTX helpers (sm_80+ ISA only) =======================
__device__ __forceinline__ uint32_t smem_u32(const void* p) {
    uint32_t a;
    asm("{ .reg .u64 t; cvta.to.shared.u64 t, %1; cvt.u32.u64 %0, t; }"
        : "=r"(a) : "l"(p));
    return a;
}

#define CP_ASYNC16(smaddr, gaddr) \
    asm volatile("cp.async.cg.shared.global [%0], [%1], 16;" \
        :: "r"(smaddr), "l"(gaddr))
#define CP_COMMIT() asm volatile("cp.async.commit_group;" ::: "memory")
#define CP_WAIT0()  asm volatile("cp.async.wait_group 0;"  ::: "memory")
#define CP_WAIT1()  asm volatile("cp.async.wait_group 1;"  ::: "memory")

#define LDMATRIX_X4(r0, r1, r2, r3, addr) \
    asm volatile("ldmatrix.sync.aligned.m8n8.x4.shared.b16 {%0,%1,%2,%3}, [%4];" \
        : "=r"(r0), "=r"(r1), "=r"(r2), "=r"(r3) : "r"(addr))

#define LDMATRIX_X4_T(r0, r1, r2, r3, addr) \
    asm volatile("ldmatrix.sync.aligned.m8n8.x4.trans.shared.b16 {%0,%1,%2,%3}, [%4];" \
        : "=r"(r0), "=r"(r1), "=r"(r2), "=r"(r3) : "r"(addr))

#define MMA_BF16(d, a, b) \
    asm volatile( \
        "mma.sync.aligned.m16n8k16.row.col.f32.bf16.bf16.f32 " \
        "{%0,%1,%2,%3}, {%4,%5,%6,%7}, {%8,%9}, {%0,%1,%2,%3};" \
        : "+f"((d)[0]), "+f"((d)[1]), "+f"((d)[2]), "+f"((d)[3]) \
        : "r"((a)[0]), "r"((a)[1]), "r"((a)[2]), "r"((a)[3]), \
          "r"((b)[0]), "r"((b)[1]))

__device__ __forceinline__ void split2_bf16(float a, float b, uint32_t& hi, uint32_t& lo) {
    __nv_bfloat16 ha = __float2bfloat16(a), hb = __float2bfloat16(b);
    __nv_bfloat162 hv, lv;
    hv.x = ha; hv.y = hb;
    lv.x = __float2bfloat16(a - __bfloat162float(ha));
    lv.y = __float2bfloat16(b - __bfloat162float(hb));
    hi = *reinterpret_cast<uint32_t*>(&hv);
    lo = *reinterpret_cast<uint32_t*>(&lv);
}

// =================================================================================
// split fp32 -> bf16 hi + bf16 lo  (a = hi + lo + O(2^-18 a))
// =================================================================================
__global__ void split_bf16(const float* __restrict__ s, __nv_bfloat16* __restrict__ h,
                           __nv_bfloat16* __restrict__ l, int n4)
{
    int i = blockIdx.x * blockDim.x + threadIdx.x;
    if (i >= n4) return;
    float4 a = ((const float4*)s)[i];
    uint32_t h0, l0, h1, l1;
    split2_bf16(a.x, a.y, h0, l0);
    split2_bf16(a.z, a.w, h1, l1);
    ((uint32_t*)h)[i * 2]     = h0;
    ((uint32_t*)h)[i * 2 + 1] = h1;
    ((uint32_t*)l)[i * 2]     = l0;
    ((uint32_t*)l)[i * 2 + 1] = l1;
}

// 4 weight matrices in one launch (blockIdx.y selects); each HIDDEN*HIDDEN
__global__ void split_bf16_w4(const float* __restrict__ s0, const float* __restrict__ s1,
                              const float* __restrict__ s2, const float* __restrict__ s3,
                              __nv_bfloat16* __restrict__ h0p, __nv_bfloat16* __restrict__ l0p,
                              __nv_bfloat16* __restrict__ h1p, __nv_bfloat16* __restrict__ l1p,
                              __nv_bfloat16* __restrict__ h2p, __nv_bfloat16* __restrict__ l2p,
                              __nv_bfloat16* __restrict__ h3p, __nv_bfloat16* __restrict__ l3p,
                              int n4)
{
    int i = blockIdx.x * blockDim.x + threadIdx.x;
    if (i >= n4) return;
    const float* s;
    __nv_bfloat16 *h, *l;
    switch (blockIdx.y) {
        case 0:  s = s0; h = h0p; l = l0p; break;
        case 1:  s = s1; h = h1p; l = l1p; break;
        case 2:  s = s2; h = h2p; l = l2p; break;
        default: s = s3; h = h3p; l = l3p; break;
    }
    float4 a = ((const float4*)s)[i];
    uint32_t hx, lx, hy, ly;
    split2_bf16(a.x, a.y, hx, lx);
    split2_bf16(a.z, a.w, hy, ly);
    ((uint32_t*)h)[i * 2]     = hx;
    ((uint32_t*)h)[i * 2 + 1] = hy;
    ((uint32_t*)l)[i * 2]     = lx;
    ((uint32_t*)l)[i * 2 + 1] = ly;
}

// =================================================================================
// HMMA GEMM v3:  C[M,N] = A[M,K] * B[N,K]^T, bf16x3 emulated fp32.
// CTA tile 128x128, 8 warps (4M x 2N), K-chunk 32 bf16, swizzled 64B-pitch smem,
// 3-stage cp.async pipeline, one __syncthreads per chunk,
// term-outer MMA ordering (same-accumulator MMAs spaced 4 apart).
// fused=1: grid.x=48 -> sel=bx>>4 picks {Q: f32 scatter, K: f32 scatter, V: bf16
//          hi/lo scatter}; fused=0: grid.x=16, C0 fp32 row-major.
// =================================================================================
#define GTILE2  8192               // 128 rows x 64 B
#define GSTAGE2 (4 * GTILE2)       // Ah, Al, Bh, Bl = 32768 B
#define GSMEM2  (3 * GSTAGE2)      // 98304 B -> 2 CTAs/SM

#define GSWZ(row, kc) ((uint32_t)((row) * 64 + ((((kc) ^ (((row) >> 1) & 3))) << 4)))

__device__ __forceinline__ void gemm_load_stage2(
    uint32_t sbase, int buf,
    const __nv_bfloat16* __restrict__ Ah, const __nv_bfloat16* __restrict__ Al,
    const __nv_bfloat16* __restrict__ Bh, const __nv_bfloat16* __restrict__ Bl,
    int aRow0, int bRow0, int koff, int K, int tid)
{
    const uint32_t sb = sbase + buf * GSTAGE2;
    const int idx0 = tid;            // 0..255
    const int idx1 = tid + 256;      // 256..511
    const int row0 = idx0 >> 2, kc0 = idx0 & 3;
    const int row1 = idx1 >> 2, kc1 = idx1 & 3;
    const uint32_t so0 = GSWZ(row0, kc0);
    const uint32_t so1 = GSWZ(row1, kc1);
    const size_t ga0 = (size_t)(aRow0 + row0) * K + koff + kc0 * 8;
    const size_t ga1 = (size_t)(aRow0 + row1) * K + koff + kc1 * 8;
    const size_t gb0 = (size_t)(bRow0 + row0) * K + koff + kc0 * 8;
    const size_t gb1 = (size_t)(bRow0 + row1) * K + koff + kc1 * 8;
    CP_ASYNC16(sb + so0,              (const void*)(Ah + ga0));
    CP_ASYNC16(sb + so1,              (const void*)(Ah + ga1));
    CP_ASYNC16(sb + GTILE2 + so0,     (const void*)(Al + ga0));
    CP_ASYNC16(sb + GTILE2 + so1,     (const void*)(Al + ga1));
    CP_ASYNC16(sb + 2 * GTILE2 + so0, (const void*)(Bh + gb0));
    CP_ASYNC16(sb + 2 * GTILE2 + so1, (const void*)(Bh + gb1));
    CP_ASYNC16(sb + 3 * GTILE2 + so0, (const void*)(Bl + gb0));
    CP_ASYNC16(sb + 3 * GTILE2 + so1, (const void*)(Bl + gb1));
}

__global__ void __launch_bounds__(256, 2)
gemm_mma(const __nv_bfloat16* __restrict__ Ah, const __nv_bfloat16* __restrict__ Al,
         const __nv_bfloat16* __restrict__ B0h, const __nv_bfloat16* __restrict__ B0l,
         const __nv_bfloat16* __restrict__ B1h, const __nv_bfloat16* __restrict__ B1l,
         const __nv_bfloat16* __restrict__ B2h, const __nv_bfloat16* __restrict__ B2l,
         float* __restrict__ C0, float* __restrict__ C1,
         __nv_bfloat16* __restrict__ C2h, __nv_bfloat16* __restrict__ C2l,
         int K, int N, int fused)
{
    extern __shared__ char sm[];
    const uint32_t sbase = smem_u32(sm);
    const int tid  = threadIdx.x;
    const int wid  = tid >> 5;
    const int lane = tid & 31;
    const int wm   = wid & 3;
    const int wn   = wid >> 2;
    const int sel  = fused ? (blockIdx.x >> 4) : 0;     // 0=Q/plain, 1=K, 2=V
    const int bn   = fused ? (blockIdx.x & 15) : blockIdx.x;
    const int bm   = blockIdx.y;
    const int aRow0 = bm * 128;
    const int bRow0 = bn * 128;
    const int NKC   = K >> 5;

    const __nv_bfloat16* Bh = (sel == 0) ? B0h : (sel == 1) ? B1h : B2h;
    const __nv_bfloat16* Bl = (sel == 0) ? B0l : (sel == 1) ? B1l : B2l;

    float acc[2][8][4];
    #pragma unroll
    for (int mt = 0; mt < 2; mt++)
        #pragma unroll
        for (int nt = 0; nt < 8; nt++)
            #pragma unroll
            for (int e = 0; e < 4; e++) acc[mt][nt][e] = 0.0f;

    const uint32_t lrow  = lane & 15;
    const uint32_t khalf = lane >> 4;          // 0/1
    const uint32_t swz   = (lrow >> 1) & 3;

    // preload stages 0, 1
    gemm_load_stage2(sbase, 0, Ah, Al, Bh, Bl, aRow0, bRow0, 0,  K, tid); CP_COMMIT();
    gemm_load_stage2(sbase, 1, Ah, Al, Bh, Bl, aRow0, bRow0, 32, K, tid); CP_COMMIT();

    int scur = 0, sld = 2;
    for (int c = 0; c < NKC; c++) {
        if (c + 1 < NKC) { CP_WAIT1(); } else { CP_WAIT0(); }
        __syncthreads();

        // prefetch chunk c+2 into the stage consumed at chunk c-1
        if (c + 2 < NKC) {
            gemm_load_stage2(sbase, sld, Ah, Al, Bh, Bl,
                             aRow0, bRow0, (c + 2) * 32, K, tid);
            CP_COMMIT();
            if (++sld == 3) sld = 0;
        }

        const uint32_t abase = sbase + scur * GSTAGE2;
        const uint32_t bbase = abase + 2 * GTILE2;
        if (++scur == 3) scur = 0;

        #pragma unroll
        for (int kk = 0; kk < 2; kk++) {
            const uint32_t sw16 = (((kk * 2 + khalf) ^ swz) << 4);

            uint32_t ah_[2][4], al_[2][4];
            #pragma unroll
            for (int mt = 0; mt < 2; mt++) {
                const uint32_t ra = abase + ((wm * 32 + mt * 16 + lrow) << 6) + sw16;
                LDMATRIX_X4(ah_[mt][0], ah_[mt][1], ah_[mt][2], ah_[mt][3], ra);
                LDMATRIX_X4(al_[mt][0], al_[mt][1], al_[mt][2], al_[mt][3], ra + GTILE2);
            }

            // B fragments: [buf][bh0,bh1,bl0,bl1][2], double buffered over p
            uint32_t bfr[2][4][2];
            #define LOADB(p, bb) do { \
                const uint32_t rb = bbase + ((wn * 64 + (p) * 16 + lrow) << 6) + sw16; \
                uint32_t t0, t1, t2, t3; \
                LDMATRIX_X4(t0, t1, t2, t3, rb); \
                (bb)[0][0] = t0; (bb)[0][1] = t2; (bb)[1][0] = t1; (bb)[1][1] = t3; \
                LDMATRIX_X4(t0, t1, t2, t3, rb + GTILE2); \
                (bb)[2][0] = t0; (bb)[2][1] = t2; (bb)[3][0] = t1; (bb)[3][1] = t3; \
            } while (0)

            LOADB(0, bfr[0]);
            #pragma unroll
            for (int p = 0; p < 4; p++) {
                if (p < 3) LOADB(p + 1, bfr[(p + 1) & 1]);
                uint32_t (*bc)[2] = bfr[p & 1];
                // term-outer ordering: same-accumulator MMAs spaced 4 apart,
                // per-accumulator term order unchanged (hh -> hl -> lh)
                MMA_BF16(acc[0][2*p],   ah_[0], bc[0]);   // hh
                MMA_BF16(acc[0][2*p+1], ah_[0], bc[1]);
                MMA_BF16(acc[1][2*p],   ah_[1], bc[0]);
                MMA_BF16(acc[1][2*p+1], ah_[1], bc[1]);
                MMA_BF16(acc[0][2*p],   ah_[0], bc[2]);   // hl
                MMA_BF16(acc[0][2*p+1], ah_[0], bc[3]);
                MMA_BF16(acc[1][2*p],   ah_[1], bc[2]);
                MMA_BF16(acc[1][2*p+1], ah_[1], bc[3]);
                MMA_BF16(acc[0][2*p],   al_[0], bc[0]);   // lh
                MMA_BF16(acc[0][2*p+1], al_[0], bc[1]);
                MMA_BF16(acc[1][2*p],   al_[1], bc[0]);
                MMA_BF16(acc[1][2*p+1], al_[1], bc[1]);
            }
            #undef LOADB
        }
    }

    // ---- epilogue ----
    const int tr = lane >> 2;
    const int tc = (lane & 3) * 2;
    #pragma unroll
    for (int mt = 0; mt < 2; mt++) {
        #pragma unroll
        for (int rr = 0; rr < 2; rr++) {
            const int m = aRow0 + wm * 32 + mt * 16 + rr * 8 + tr;
            size_t base;
            if (!fused) {
                base = (size_t)m * N + bn * 128;
            } else {
                const int bb = m >> 11;
                const int t  = m & 2047;
                base = (((size_t)(bb * NHEADS + bn)) * SEQ + t) << 7;
            }
            if (fused && sel == 2) {
                #pragma unroll
                for (int nt = 0; nt < 8; nt++) {
                    uint32_t hi, lo;
                    split2_bf16(acc[mt][nt][rr * 2 + 0], acc[mt][nt][rr * 2 + 1], hi, lo);
                    const size_t idx = base + wn * 64 + nt * 8 + tc;
                    *(uint32_t*)(C2h + idx) = hi;
                    *(uint32_t*)(C2l + idx) = lo;
                }
            } else {
                float* dst = ((fused && sel == 1) ? C1 : C0) + base;
                #pragma unroll
                for (int nt = 0; nt < 8; nt++) {
                    float2 v;
                    v.x = acc[mt][nt][rr * 2 + 0];
                    v.y = acc[mt][nt][rr * 2 + 1];
                    *(float2*)(dst + wn * 64 + nt * 8 + tc) = v;
                }
            }
        }
    }
}

// =================================================================================
// RoPE + split: reads fp32 q,k [B,H,T,D], writes bf16 hi/lo splits.
// =================================================================================
__global__ void rope_split(const float* __restrict__ q, const float* __restrict__ k,
                           __nv_bfloat16* __restrict__ qbh, __nv_bfloat16* __restrict__ qbl,
                           __nv_bfloat16* __restrict__ kbh, __nv_bfloat16* __restrict__ kbl)
{
    const int idx = blockIdx.x * blockDim.x + threadIdx.x;
    const int i   = idx & 63;
    const int row = idx >> 6;
    const int t   = row & (SEQ - 1);

    const float inv = exp2f(-(float)i * 0.20762050593046014f);  // 10000^(-i/64)
    const float ang = (float)t * inv;
    float s, c;
    sincosf(ang, &s, &c);

    const size_t base = (size_t)row * HDIM;
    const float q1 = q[base + i], q2 = q[base + i + 64];
    const float k1 = k[base + i], k2 = k[base + i + 64];
    const float qa = q1 * c - q2 * s, qb = q2 * c + q1 * s;
    const float ka = k1 * c - k2 * s, kb = k2 * c + k1 * s;

    __nv_bfloat16 h;
    h = __float2bfloat16(qa); qbh[base + i]      = h; qbl[base + i]      = __float2bfloat16(qa - __bfloat162float(h));
    h = __float2bfloat16(qb); qbh[base + i + 64] = h; qbl[base + i + 64] = __float2bfloat16(qb - __bfloat162float(h));
    h = __float2bfloat16(ka); kbh[base + i]      = h; kbl[base + i]      = __float2bfloat16(ka - __bfloat162float(h));
    h = __float2bfloat16(kb); kbh[base + i + 64] = h; kbl[base + i + 64] = __float2bfloat16(kb - __bfloat162float(h));
}

// =================================================================================
// HMMA flash attention, causal, bf16x3. BM=128 (8 warps x 16 rows), BN=64, D=128.
// Double-buffered K/V stages (cp.async). Output: bf16 hi/lo splits [B,T,C].
// =================================================================================
#define FPB      272                  // smem row pitch bytes (136 bf16)
#define FQ_TILE  (128 * FPB)          // 34816
#define FKV_TILE (64 * FPB)           // 17408
#define FSM_KV(s) (2 * FQ_TILE + (s) * (4 * FKV_TILE))
#define FSMEM    (2 * FQ_TILE + 2 * 4 * FKV_TILE)   // 208896

__device__ __forceinline__ void fa_load_kv(
    uint32_t sbase, int s,
    const __nv_bfloat16* __restrict__ kh, const __nv_bfloat16* __restrict__ kl,
    const __nv_bfloat16* __restrict__ vh, const __nv_bfloat16* __restrict__ vl,
    size_t off, int tid)
{
    const uint32_t sb = sbase + FSM_KV(s);
    #pragma unroll
    for (int it = 0; it < 4; it++) {
        const int q   = tid + it * 256;   // 0..1023
        const int row = q >> 4;           // 0..63
        const int ck  = q & 15;
        const uint32_t so = row * FPB + ck * 16;
        const size_t go = off + (size_t)row * HDIM + ck * 8;
        CP_ASYNC16(sb + so,                (const void*)(kh + go));
        CP_ASYNC16(sb + FKV_TILE + so,     (const void*)(kl + go));
        CP_ASYNC16(sb + 2 * FKV_TILE + so, (const void*)(vh + go));
        CP_ASYNC16(sb + 3 * FKV_TILE + so, (const void*)(vl + go));
    }
}

__global__ void __launch_bounds__(256, 1)
flash_mma(const __nv_bfloat16* __restrict__ qh, const __nv_bfloat16* __restrict__ ql,
          const __nv_bfloat16* __restrict__ kh, const __nv_bfloat16* __restrict__ kl,
          const __nv_bfloat16* __restrict__ vh, const __nv_bfloat16* __restrict__ vl,
          __nv_bfloat16* __restrict__ oh, __nv_bfloat16* __restrict__ ol)
{
    extern __shared__ char sm[];
    const uint32_t sbase = smem_u32(sm);
    const int tid  = threadIdx.x;
    const int wid  = tid >> 5;
    const int lane = tid & 31;
    const int bh   = blockIdx.y;
    const int qi   = (gridDim.x - 1) - blockIdx.x;   // heavy q-tiles first
    const float scale = 0.08838834764831845f;        // 1/sqrt(128)

    // ---- load Q hi/lo into smem ----
    const size_t qoff = ((size_t)bh * SEQ + (size_t)qi * 128) * HDIM;
    for (int idx = tid; idx < 128 * 16; idx += 256) {
        const int row = idx >> 4, ck = idx & 15;
        const uint32_t so = row * FPB + ck * 16;
        *(uint4*)(sm + so)           = *(const uint4*)(qh + qoff + (size_t)row * HDIM + ck * 8);
        *(uint4*)(sm + FQ_TILE + so) = *(const uint4*)(ql + qoff + (size_t)row * HDIM + ck * 8);
    }

    const int nkv = 2 * qi + 2;
    const size_t bhoff = (size_t)bh * SEQ * HDIM;
    fa_load_kv(sbase, 0, kh, kl, vh, vl, bhoff, tid);               CP_COMMIT();
    fa_load_kv(sbase, 1, kh, kl, vh, vl, bhoff + 64 * HDIM, tid);   CP_COMMIT();

    float oacc[16][4];
    #pragma unroll
    for (int nt = 0; nt < 16; nt++)
        #pragma unroll
        for (int e = 0; e < 4; e++) oacc[nt][e] = 0.0f;
    float m1 = -1e30f, m2 = -1e30f, l1 = 0.0f, l2 = 0.0f;

    const int r1 = lane >> 2;            // 0..7
    const int c2 = (lane & 3) * 2;
    const uint32_t qrow = sbase + (wid * 16 + (lane & 15)) * FPB + (lane >> 4) * 16;
    const uint32_t lrow_off = (lane & 15) * FPB + (lane >> 4) * 16;

    for (int j = 0; j < nkv; j++) {
        if (j + 1 < nkv) { CP_WAIT1(); } else { CP_WAIT0(); }
        __syncthreads();

        const uint32_t kvb = sbase + FSM_KV(j & 1);
        const bool active = (j * 64 <= qi * 128 + wid * 16 + 15);
        if (active) {
            // ---- S = Q K^T (3-term bf16) ----
            float sacc[8][4];
            #pragma unroll
            for (int nt = 0; nt < 8; nt++)
                #pragma unroll
                for (int e = 0; e < 4; e++) sacc[nt][e] = 0.0f;

            const uint32_t krow = kvb + lrow_off;
            #pragma unroll
            for (int kd = 0; kd < 8; kd++) {
                uint32_t ah4[4], al4[4];
                LDMATRIX_X4(ah4[0], ah4[1], ah4[2], ah4[3], qrow + kd * 32);
                LDMATRIX_X4(al4[0], al4[1], al4[2], al4[3], qrow + FQ_TILE + kd * 32);
                #pragma unroll
                for (int p = 0; p < 4; p++) {
                    uint32_t t0, t1, t2, t3;
                    uint32_t bhf[2][2], blf[2][2];
                    LDMATRIX_X4(t0, t1, t2, t3, krow + p * (16 * FPB) + kd * 32);
                    bhf[0][0] = t0; bhf[0][1] = t2; bhf[1][0] = t1; bhf[1][1] = t3;
                    LDMATRIX_X4(t0, t1, t2, t3, krow + FKV_TILE + p * (16 * FPB) + kd * 32);
                    blf[0][0] = t0; blf[0][1] = t2; blf[1][0] = t1; blf[1][1] = t3;
                    // 2-way interleave: same-acc MMAs spaced 2 apart
                    MMA_BF16(sacc[2*p],   ah4, bhf[0]);
                    MMA_BF16(sacc[2*p+1], ah4, bhf[1]);
                    MMA_BF16(sacc[2*p],   ah4, blf[0]);
                    MMA_BF16(sacc[2*p+1], ah4, blf[1]);
                    MMA_BF16(sacc[2*p],   al4, bhf[0]);
                    MMA_BF16(sacc[2*p+1], al4, bhf[1]);
                }
            }

            // ---- scale + causal mask + online softmax ----
            const bool need_mask = (j * 64 + 63 > qi * 128 + wid * 16);
            const int grow1 = qi * 128 + wid * 16 + r1;
            float mx1 = m1, mx2 = m2;
            #pragma unroll
            for (int nt = 0; nt < 8; nt++) {
                #pragma unroll
                for (int e = 0; e < 4; e++) sacc[nt][e] *= scale;
                if (need_mask) {
                    const int col = j * 64 + nt * 8 + c2;
                    if (col     > grow1)     sacc[nt][0] = -1e30f;
                    if (col + 1 > grow1)     sacc[nt][1] = -1e30f;
                    if (col     > grow1 + 8) sacc[nt][2] = -1e30f;
                    if (col + 1 > grow1 + 8) sacc[nt][3] = -1e30f;
                }
                mx1 = fmaxf(mx1, fmaxf(sacc[nt][0], sacc[nt][1]));
                mx2 = fmaxf(mx2, fmaxf(sacc[nt][2], sacc[nt][3]));
            }
            mx1 = fmaxf(mx1, __shfl_xor_sync(0xffffffffu, mx1, 1));
            mx1 = fmaxf(mx1, __shfl_xor_sync(0xffffffffu, mx1, 2));
            mx2 = fmaxf(mx2, __shfl_xor_sync(0xffffffffu, mx2, 1));
            mx2 = fmaxf(mx2, __shfl_xor_sync(0xffffffffu, mx2, 2));

            const float alpha1 = __expf(m1 - mx1);
            const float alpha2 = __expf(m2 - mx2);
            m1 = mx1; m2 = mx2;

            float sum1 = 0.0f, sum2 = 0.0f;
            #pragma unroll
            for (int nt = 0; nt < 8; nt++) {
                sacc[nt][0] = __expf(sacc[nt][0] - mx1);
                sacc[nt][1] = __expf(sacc[nt][1] - mx1);
                sacc[nt][2] = __expf(sacc[nt][2] - mx2);
                sacc[nt][3] = __expf(sacc[nt][3] - mx2);
                sum1 += sacc[nt][0] + sacc[nt][1];
                sum2 += sacc[nt][2] + sacc[nt][3];
            }
            l1 = l1 * alpha1 + sum1;    // per-lane partial; quad-reduced at end
            l2 = l2 * alpha2 + sum2;

            #pragma unroll
            for (int nt = 0; nt < 16; nt++) {
                oacc[nt][0] *= alpha1; oacc[nt][1] *= alpha1;
                oacc[nt][2] *= alpha2; oacc[nt][3] *= alpha2;
            }

            // ---- O += P V (3-term bf16) ----
            const uint32_t vbase = kvb + 2 * FKV_TILE;
            #pragma unroll
            for (int g = 0; g < 4; g++) {
                uint32_t pha[4], pla[4];
                split2_bf16(sacc[2*g][0],   sacc[2*g][1],   pha[0], pla[0]);
                split2_bf16(sacc[2*g][2],   sacc[2*g][3],   pha[1], pla[1]);
                split2_bf16(sacc[2*g+1][0], sacc[2*g+1][1], pha[2], pla[2]);
                split2_bf16(sacc[2*g+1][2], sacc[2*g+1][3], pha[3], pla[3]);

                const uint32_t va = vbase + g * (16 * FPB) + lrow_off;
                #pragma unroll
                for (int pp = 0; pp < 8; pp++) {
                    uint32_t t0, t1, t2, t3;
                    LDMATRIX_X4_T(t0, t1, t2, t3, va + pp * 32);
                    uint32_t vh0[2] = { t0, t1 }, vh1[2] = { t2, t3 };
                    LDMATRIX_X4_T(t0, t1, t2, t3, va + FKV_TILE + pp * 32);
                    uint32_t vl0[2] = { t0, t1 }, vl1[2] = { t2, t3 };
                    // 2-way interleave across the two accumulators
                    MMA_BF16(oacc[2*pp],   pha, vh0);
                    MMA_BF16(oacc[2*pp+1], pha, vh1);
                    MMA_BF16(oacc[2*pp],   pla, vh0);
                    MMA_BF16(oacc[2*pp+1], pla, vh1);
                    MMA_BF16(oacc[2*pp],   pha, vl0);
                    MMA_BF16(oacc[2*pp+1], pha, vl1);
                }
            }
        }
        __syncthreads();    // all reads of stage (j&1) done before overwrite
        if (j + 2 < nkv) {
            fa_load_kv(sbase, j & 1, kh, kl, vh, vl,
                       bhoff + (size_t)(j + 2) * 64 * HDIM, tid);
            CP_COMMIT();
        }
    }

    // ---- finalize: quad-reduce l, normalize, write bf16 hi/lo [B,T,C] ----
    l1 += __shfl_xor_sync(0xffffffffu, l1, 1);
    l1 += __shfl_xor_sync(0xffffffffu, l1, 2);
    l2 += __shfl_xor_sync(0xffffffffu, l2, 1);
    l2 += __shfl_xor_sync(0xffffffffu, l2, 2);
    const float inv1 = 1.0f / l1;
    const float inv2 = 1.0f / l2;

    const int b = bh >> 4;
    const int h = bh & 15;
    const int row1 = qi * 128 + wid * 16 + r1;
    const size_t ob1 = ((size_t)(b * SEQ + row1)) * HIDDEN + h * HDIM;
    const size_t ob2 = ob1 + (size_t)8 * HIDDEN;
    #pragma unroll
    for (int nt = 0; nt < 16; nt++) {
        uint32_t hi, lo;
        split2_bf16(oacc[nt][0] * inv1, oacc[nt][1] * inv1, hi, lo);
        *(uint32_t*)(oh + ob1 + nt * 8 + c2) = hi;
        *(uint32_t*)(ol + ob1 + nt * 8 + c2) = lo;
        split2_bf16(oacc[nt][2] * inv2, oacc[nt][3] * inv2, hi, lo);
        *(uint32_t*)(oh + ob2 + nt * 8 + c2) = hi;
        *(uint32_t*)(ol + ob2 + nt * 8 + c2) = lo;
    }
}

// =================================================================================
// launch
// =================================================================================
extern "C" void kernel_launch(void* const* d_in, const int* in_sizes, int n_in,
                              void* d_out, int out_size)
{
    (void)in_sizes; (void)n_in; (void)out_size;
    const float* x  = (const float*)d_in[0];
    const float* Wq = (const float*)d_in[1];
    const float* Wk = (const float*)d_in[2];
    const float* Wv = (const float*)d_in[3];
    const float* Wo = (const float*)d_in[4];
    float* out = (float*)d_out;

    float *qp, *kp;
    __nv_bfloat16 *xh, *xl, *ah, *al;
    __nv_bfloat16 *wqh, *wql, *wkh, *wkl, *wvh, *wvl, *woh, *wol;
    __nv_bfloat16 *qbh, *qbl, *kbh, *kbl, *vbh, *vbl;
    cudaGetSymbolAddress((void**)&qp, g_q);
    cudaGetSymbolAddress((void**)&kp, g_k);
    cudaGetSymbolAddress((void**)&xh, g_xh);  cudaGetSymbolAddress((void**)&xl, g_xl);
    cudaGetSymbolAddress((void**)&ah, g_ah);  cudaGetSymbolAddress((void**)&al, g_al);
    cudaGetSymbolAddress((void**)&wqh, g_wqh); cudaGetSymbolAddress((void**)&wql, g_wql);
    cudaGetSymbolAddress((void**)&wkh, g_wkh); cudaGetSymbolAddress((void**)&wkl, g_wkl);
    cudaGetSymbolAddress((void**)&wvh, g_wvh); cudaGetSymbolAddress((void**)&wvl, g_wvl);
    cudaGetSymbolAddress((void**)&woh, g_woh); cudaGetSymbolAddress((void**)&wol, g_wol);
    cudaGetSymbolAddress((void**)&qbh, g_qbh); cudaGetSymbolAddress((void**)&qbl, g_qbl);
    cudaGetSymbolAddress((void**)&kbh, g_kbh); cudaGetSymbolAddress((void**)&kbl, g_kbl);
    cudaGetSymbolAddress((void**)&vbh, g_vbh); cudaGetSymbolAddress((void**)&vbl, g_vbl);

    cudaFuncSetAttribute(gemm_mma, cudaFuncAttributeMaxDynamicSharedMemorySize, GSMEM2);
    cudaFuncSetAttribute(flash_mma, cudaFuncAttributeMaxDynamicSharedMemorySize, FSMEM);

    const int nx4 = BT * HIDDEN / 4;        // 2097152 (x is 2x weight size!)
    const int nw4 = HIDDEN * HIDDEN / 4;    // 1048576

    split_bf16<<<nx4 / 256, 256>>>(x, xh, xl, nx4);
    split_bf16_w4<<<dim3(nw4 / 256, 4), 256>>>(Wq, Wk, Wv, Wo,
                                               wqh, wql, wkh, wkl,
                                               wvh, wvl, woh, wol, nw4);

    // fused Q/K/V projection: one launch, grid.x = 48 (16 per output)
    gemm_mma<<<dim3(48, BT / 128), 256, GSMEM2>>>(
        xh, xl, wqh, wql, wkh, wkl, wvh, wvl,
        qp, kp, vbh, vbl, HIDDEN, HIDDEN, 1);

    rope_split<<<(BATCH * NHEADS * SEQ * 64) / 256, 256>>>(qp, kp, qbh, qbl, kbh, kbl);

    flash_mma<<<dim3(SEQ / 128, BATCH * NHEADS), 256, FSMEM>>>(qbh, qbl, kbh, kbl,
                                                               vbh, vbl, ah, al);

    // output projection (plain mode)
    gemm_mma<<<dim3(16, BT / 128), 256, GSMEM2>>>(
        ah, al, woh, wol, nullptr, nullptr, nullptr, nullptr,
        out, nullptr, nullptr, nullptr, HIDDEN, HIDDEN, 0);
}